// round 1
// baseline (speedup 1.0000x reference)
#include <cuda_runtime.h>

#define T_DIM 2048
#define H_DIM 4096
#define O_DIM 4096
#define L_DIM 32
#define R_DIM 16

#define BM 128
#define BN 128
#define BK 16
#define KT (H_DIM / BK)   // 256 k-tiles

// Scratch (no allocations allowed in kernel_launch)
__device__ int   g_idx32[T_DIM];
__device__ float g_shrunk[T_DIM * R_DIM];

// ---------------------------------------------------------------------------
// Kernel 1: detect int64 vs int32 indices and convert to int32.
// int64 little-endian viewed as int32 pairs: [value, 0 or -1 sign-extension].
// Checking 1024 pairs (8KB — within bounds for either width) makes
// misclassification probability effectively zero for values in [-1, 31].
// ---------------------------------------------------------------------------
__global__ void prep_indices(const int* __restrict__ raw) {
    __shared__ int bad;
    if (threadIdx.x == 0) bad = 0;
    __syncthreads();
    for (int p = threadIdx.x; p < 1024; p += blockDim.x) {
        int lo = raw[2 * p];
        int hi = raw[2 * p + 1];
        bool ok = (hi == 0 && lo >= 0) || (hi == -1 && lo < 0);
        if (!ok) bad = 1;                       // benign race, all write 1
    }
    __syncthreads();
    const bool is64 = (bad == 0);
    for (int t = threadIdx.x; t < T_DIM; t += blockDim.x) {
        g_idx32[t] = is64 ? raw[2 * t] : raw[t];
    }
}

// ---------------------------------------------------------------------------
// Kernel 2: LoRA shrink  s[t,r] = sum_h x[t,h] * A[idx[t], r, h]
// One block (256 threads) per token. A is 8MB -> L2 resident.
// ---------------------------------------------------------------------------
__global__ __launch_bounds__(256) void shrunk_kernel(
    const float* __restrict__ x, const float* __restrict__ lora_a) {
    const int t   = blockIdx.x;
    const int tid = threadIdx.x;
    const int l   = g_idx32[t];
    if (l < 0) {
        if (tid < R_DIM) g_shrunk[t * R_DIM + tid] = 0.0f;
        return;
    }
    const float4* x4 = (const float4*)(x + (size_t)t * H_DIM);
    const float4* a4 = (const float4*)(lora_a + (size_t)l * R_DIM * H_DIM);
    const int H4 = H_DIM / 4;   // 1024

    float acc[R_DIM];
#pragma unroll
    for (int r = 0; r < R_DIM; r++) acc[r] = 0.0f;

    for (int i = tid; i < H4; i += 256) {
        float4 xv = x4[i];
#pragma unroll
        for (int r = 0; r < R_DIM; r++) {
            float4 av = a4[r * H4 + i];
            acc[r] += xv.x * av.x + xv.y * av.y + xv.z * av.z + xv.w * av.w;
        }
    }

    __shared__ float sred[R_DIM];
    if (tid < R_DIM) sred[tid] = 0.0f;
    __syncthreads();
#pragma unroll
    for (int r = 0; r < R_DIM; r++) {
        float v = acc[r];
#pragma unroll
        for (int off = 16; off > 0; off >>= 1)
            v += __shfl_down_sync(0xffffffff, v, off);
        if ((tid & 31) == 0) atomicAdd(&sred[r], v);
    }
    __syncthreads();
    if (tid < R_DIM) g_shrunk[t * R_DIM + tid] = sred[tid];
}

// ---------------------------------------------------------------------------
// Kernel 3: main GEMM  out = X @ W^T + bias + shrunk @ B[idx]^T (fused epilogue)
// 128x128x16 tiles, double-buffered smem, 256 threads, 8x8 per thread
// (split as 4+4 in each dim for conflict-free LDS.128).
// ---------------------------------------------------------------------------
__global__ __launch_bounds__(256, 2) void gemm_lora_kernel(
    const float* __restrict__ X, const float* __restrict__ W,
    const float* __restrict__ bias, const float* __restrict__ lora_b,
    float* __restrict__ out) {
    __shared__ float As[2][BK][BM];
    __shared__ float Bs[2][BK][BN];

    const int tid = threadIdx.x;
    const int tx  = tid & 15;     // 0..15  -> N
    const int ty  = tid >> 4;     // 0..15  -> M
    const int m0  = blockIdx.y * BM;
    const int n0  = blockIdx.x * BN;

    const float* Xb = X + (size_t)m0 * H_DIM;
    const float* Wb = W + (size_t)n0 * H_DIM;

    // Each thread stages 2 float4 per matrix per tile.
    // slot s = tid + 256*i : row = s>>2 (0..127), k4 = (s&3)*4
    float4 ra[2], rb[2];

    const int r0 = (tid + 0)   >> 2, k40 = ((tid + 0)   & 3) * 4;
    const int r1 = (tid + 256) >> 2, k41 = ((tid + 256) & 3) * 4;

    float acc[8][8];
#pragma unroll
    for (int i = 0; i < 8; i++)
#pragma unroll
        for (int j = 0; j < 8; j++) acc[i][j] = 0.0f;

    // --- prologue: tile 0 ---
    ra[0] = *(const float4*)(Xb + (size_t)r0 * H_DIM + k40);
    ra[1] = *(const float4*)(Xb + (size_t)r1 * H_DIM + k41);
    rb[0] = *(const float4*)(Wb + (size_t)r0 * H_DIM + k40);
    rb[1] = *(const float4*)(Wb + (size_t)r1 * H_DIM + k41);
    {
        As[0][k40 + 0][r0] = ra[0].x; As[0][k40 + 1][r0] = ra[0].y;
        As[0][k40 + 2][r0] = ra[0].z; As[0][k40 + 3][r0] = ra[0].w;
        As[0][k41 + 0][r1] = ra[1].x; As[0][k41 + 1][r1] = ra[1].y;
        As[0][k41 + 2][r1] = ra[1].z; As[0][k41 + 3][r1] = ra[1].w;
        Bs[0][k40 + 0][r0] = rb[0].x; Bs[0][k40 + 1][r0] = rb[0].y;
        Bs[0][k40 + 2][r0] = rb[0].z; Bs[0][k40 + 3][r0] = rb[0].w;
        Bs[0][k41 + 0][r1] = rb[1].x; Bs[0][k41 + 1][r1] = rb[1].y;
        Bs[0][k41 + 2][r1] = rb[1].z; Bs[0][k41 + 3][r1] = rb[1].w;
    }
    __syncthreads();

    int cur = 0;
    for (int kt = 0; kt < KT; kt++) {
        if (kt + 1 < KT) {
            const int koff = (kt + 1) * BK;
            ra[0] = *(const float4*)(Xb + (size_t)r0 * H_DIM + koff + k40);
            ra[1] = *(const float4*)(Xb + (size_t)r1 * H_DIM + koff + k41);
            rb[0] = *(const float4*)(Wb + (size_t)r0 * H_DIM + koff + k40);
            rb[1] = *(const float4*)(Wb + (size_t)r1 * H_DIM + koff + k41);
        }
#pragma unroll
        for (int kk = 0; kk < BK; kk++) {
            float4 a0 = *(const float4*)&As[cur][kk][ty * 4];
            float4 a1 = *(const float4*)&As[cur][kk][64 + ty * 4];
            float4 b0 = *(const float4*)&Bs[cur][kk][tx * 4];
            float4 b1 = *(const float4*)&Bs[cur][kk][64 + tx * 4];
            const float av[8] = {a0.x, a0.y, a0.z, a0.w, a1.x, a1.y, a1.z, a1.w};
            const float bv[8] = {b0.x, b0.y, b0.z, b0.w, b1.x, b1.y, b1.z, b1.w};
#pragma unroll
            for (int i = 0; i < 8; i++)
#pragma unroll
                for (int j = 0; j < 8; j++)
                    acc[i][j] += av[i] * bv[j];
        }
        if (kt + 1 < KT) {
            const int nb = cur ^ 1;
            As[nb][k40 + 0][r0] = ra[0].x; As[nb][k40 + 1][r0] = ra[0].y;
            As[nb][k40 + 2][r0] = ra[0].z; As[nb][k40 + 3][r0] = ra[0].w;
            As[nb][k41 + 0][r1] = ra[1].x; As[nb][k41 + 1][r1] = ra[1].y;
            As[nb][k41 + 2][r1] = ra[1].z; As[nb][k41 + 3][r1] = ra[1].w;
            Bs[nb][k40 + 0][r0] = rb[0].x; Bs[nb][k40 + 1][r0] = rb[0].y;
            Bs[nb][k40 + 2][r0] = rb[0].z; Bs[nb][k40 + 3][r0] = rb[0].w;
            Bs[nb][k41 + 0][r1] = rb[1].x; Bs[nb][k41 + 1][r1] = rb[1].y;
            Bs[nb][k41 + 2][r1] = rb[1].z; Bs[nb][k41 + 3][r1] = rb[1].w;
            __syncthreads();
            cur = nb;
        }
    }

    // --- epilogue: + bias + LoRA expand, write out ---
    // column offsets for this thread: c0 = tx*4, c1 = 64 + tx*4
    const int c0 = tx * 4, c1 = 64 + tx * 4;
    float4 bias0 = *(const float4*)(bias + n0 + c0);
    float4 bias1 = *(const float4*)(bias + n0 + c1);
    const float bvec[8] = {bias0.x, bias0.y, bias0.z, bias0.w,
                           bias1.x, bias1.y, bias1.z, bias1.w};

#pragma unroll
    for (int i = 0; i < 8; i++) {
        const int rowoff = (i < 4) ? (ty * 4 + i) : (64 + ty * 4 + (i - 4));
        const int row = m0 + rowoff;
        const int l = g_idx32[row];

        float s[R_DIM];
        if (l >= 0) {
            const float4* s4 = (const float4*)(g_shrunk + row * R_DIM);
#pragma unroll
            for (int q = 0; q < 4; q++) {
                float4 v = s4[q];
                s[q * 4 + 0] = v.x; s[q * 4 + 1] = v.y;
                s[q * 4 + 2] = v.z; s[q * 4 + 3] = v.w;
            }
        }

        float res[8];
#pragma unroll
        for (int j = 0; j < 8; j++) {
            const int col = n0 + ((j < 4) ? (c0 + j) : (c1 + (j - 4)));
            float v = acc[i][j] + bvec[j];
            if (l >= 0) {
                const float4* b4 =
                    (const float4*)(lora_b + ((size_t)l * O_DIM + col) * R_DIM);
                float dot = 0.0f;
#pragma unroll
                for (int q = 0; q < 4; q++) {
                    float4 bb = b4[q];
                    dot += s[q * 4 + 0] * bb.x + s[q * 4 + 1] * bb.y +
                           s[q * 4 + 2] * bb.z + s[q * 4 + 3] * bb.w;
                }
                v += dot;
            }
            res[j] = v;
        }
        float* op = out + (size_t)row * O_DIM + n0;
        *(float4*)(op + c0) = make_float4(res[0], res[1], res[2], res[3]);
        *(float4*)(op + c1) = make_float4(res[4], res[5], res[6], res[7]);
    }
}

// ---------------------------------------------------------------------------
extern "C" void kernel_launch(void* const* d_in, const int* in_sizes, int n_in,
                              void* d_out, int out_size) {
    const float* x      = (const float*)d_in[0];  // (T, H)
    const float* weight = (const float*)d_in[1];  // (O, H)
    const float* bias   = (const float*)d_in[2];  // (O,)
    const float* lora_a = (const float*)d_in[3];  // (L, R, H)
    const float* lora_b = (const float*)d_in[4];  // (L, O, R)
    const int*   rawidx = (const int*)d_in[5];    // (T,) int32 or int64
    float* out = (float*)d_out;                   // (T, O)

    prep_indices<<<1, 256>>>(rawidx);
    shrunk_kernel<<<T_DIM, 256>>>(x, lora_a);
    dim3 grid(O_DIM / BN, T_DIM / BM);            // (32, 16)
    gemm_lora_kernel<<<grid, 256>>>(x, weight, bias, lora_b, out);
}

// round 3
// speedup vs baseline: 2.1905x; 2.1905x over previous
#include <cuda_runtime.h>
#include <cuda_bf16.h>
#include <cstdint>

#define T_DIM 2048
#define H_DIM 4096
#define O_DIM 4096
#define R_DIM 16

#define BM 128
#define BN 128
#define BK 32
#define KT_N (H_DIM / BK)          // 128 k-tiles
#define STAGES 4
#define MAT_BYTES 8192             // 128 rows x 64 bytes (32 bf16)
#define STAGE_BYTES (4 * MAT_BYTES)
#define DYN_SMEM (STAGES * STAGE_BYTES)

// ---------------- device scratch ----------------
__device__ int   g_idx32[T_DIM];
__device__ float g_shrunk[T_DIM * R_DIM];
__device__ __nv_bfloat16 g_Xhi[T_DIM * H_DIM];
__device__ __nv_bfloat16 g_Xlo[T_DIM * H_DIM];
__device__ __nv_bfloat16 g_Whi[O_DIM * H_DIM];
__device__ __nv_bfloat16 g_Wlo[O_DIM * H_DIM];

// ---------------- helpers ----------------
__device__ __forceinline__ uint32_t smem_u32(const void* p) {
    uint32_t a;
    asm("{ .reg .u64 t; cvta.to.shared.u64 t, %1; cvt.u32.u64 %0, t; }"
        : "=r"(a) : "l"(p));
    return a;
}

__device__ __forceinline__ uint32_t swz(uint32_t o) {
    return o ^ ((o >> 3) & 0x30);   // 64B-row swizzle: cols[5:4] ^= rowbits
}

#define CP_ASYNC16(dst, src) \
    asm volatile("cp.async.cg.shared.global [%0], [%1], 16;" :: "r"(dst), "l"(src))
#define CP_COMMIT() asm volatile("cp.async.commit_group;" ::: "memory")
#define CP_WAIT2()  asm volatile("cp.async.wait_group 2;" ::: "memory")

#define LDSM4(d0, d1, d2, d3, a)                                          \
    asm volatile("ldmatrix.sync.aligned.m8n8.x4.shared.b16 {%0,%1,%2,%3}, [%4];" \
                 : "=r"(d0), "=r"(d1), "=r"(d2), "=r"(d3) : "r"(a))

__device__ __forceinline__ void mma16816(float* c, const uint32_t* a,
                                         uint32_t b0, uint32_t b1) {
    asm volatile(
        "mma.sync.aligned.m16n8k16.row.col.f32.bf16.bf16.f32 "
        "{%0,%1,%2,%3}, {%4,%5,%6,%7}, {%8,%9}, {%0,%1,%2,%3};"
        : "+f"(c[0]), "+f"(c[1]), "+f"(c[2]), "+f"(c[3])
        : "r"(a[0]), "r"(a[1]), "r"(a[2]), "r"(a[3]), "r"(b0), "r"(b1));
}

// ---------------------------------------------------------------------------
// Kernel 1: detect int64 vs int32 indices, convert to int32.
// ---------------------------------------------------------------------------
__global__ void prep_indices(const int* __restrict__ raw) {
    __shared__ int bad;
    if (threadIdx.x == 0) bad = 0;
    __syncthreads();
    for (int p = threadIdx.x; p < 1024; p += blockDim.x) {
        int lo = raw[2 * p], hi = raw[2 * p + 1];
        bool ok = (hi == 0 && lo >= 0) || (hi == -1 && lo < 0);
        if (!ok) bad = 1;
    }
    __syncthreads();
    const bool is64 = (bad == 0);
    for (int t = threadIdx.x; t < T_DIM; t += blockDim.x)
        g_idx32[t] = is64 ? raw[2 * t] : raw[t];
}

// ---------------------------------------------------------------------------
// Kernels 2a/2b: fp32 -> bf16 hi/lo split
// ---------------------------------------------------------------------------
__device__ __forceinline__ void split4(float4 v, uint2& ph, uint2& pl) {
    __nv_bfloat16 hx = __float2bfloat16(v.x), hy = __float2bfloat16(v.y);
    __nv_bfloat16 hz = __float2bfloat16(v.z), hw = __float2bfloat16(v.w);
    __nv_bfloat16 lx = __float2bfloat16(v.x - __bfloat162float(hx));
    __nv_bfloat16 ly = __float2bfloat16(v.y - __bfloat162float(hy));
    __nv_bfloat16 lz = __float2bfloat16(v.z - __bfloat162float(hz));
    __nv_bfloat16 lw = __float2bfloat16(v.w - __bfloat162float(hw));
    ph.x = ((uint32_t)__bfloat16_as_ushort(hy) << 16) | __bfloat16_as_ushort(hx);
    ph.y = ((uint32_t)__bfloat16_as_ushort(hw) << 16) | __bfloat16_as_ushort(hz);
    pl.x = ((uint32_t)__bfloat16_as_ushort(ly) << 16) | __bfloat16_as_ushort(lx);
    pl.y = ((uint32_t)__bfloat16_as_ushort(lw) << 16) | __bfloat16_as_ushort(lz);
}

__global__ void convert_x(const float* __restrict__ src) {
    int i = blockIdx.x * blockDim.x + threadIdx.x;
    if (i >= T_DIM * H_DIM / 4) return;
    uint2 ph, pl;
    split4(((const float4*)src)[i], ph, pl);
    ((uint2*)g_Xhi)[i] = ph;
    ((uint2*)g_Xlo)[i] = pl;
}

__global__ void convert_w(const float* __restrict__ src) {
    int i = blockIdx.x * blockDim.x + threadIdx.x;
    if (i >= O_DIM * H_DIM / 4) return;
    uint2 ph, pl;
    split4(((const float4*)src)[i], ph, pl);
    ((uint2*)g_Whi)[i] = ph;
    ((uint2*)g_Wlo)[i] = pl;
}

// ---------------------------------------------------------------------------
// Kernel 3: LoRA shrink  s[t,r] = sum_h x[t,h] * A[idx[t], r, h]
// ---------------------------------------------------------------------------
__global__ __launch_bounds__(256) void shrunk_kernel(
    const float* __restrict__ x, const float* __restrict__ lora_a) {
    const int t = blockIdx.x, tid = threadIdx.x;
    const int l = g_idx32[t];
    if (l < 0) {
        if (tid < R_DIM) g_shrunk[t * R_DIM + tid] = 0.0f;
        return;
    }
    const float4* x4 = (const float4*)(x + (size_t)t * H_DIM);
    const float4* a4 = (const float4*)(lora_a + (size_t)l * R_DIM * H_DIM);
    const int H4 = H_DIM / 4;
    float acc[R_DIM];
#pragma unroll
    for (int r = 0; r < R_DIM; r++) acc[r] = 0.0f;
    for (int i = tid; i < H4; i += 256) {
        float4 xv = x4[i];
#pragma unroll
        for (int r = 0; r < R_DIM; r++) {
            float4 av = a4[r * H4 + i];
            acc[r] += xv.x * av.x + xv.y * av.y + xv.z * av.z + xv.w * av.w;
        }
    }
    __shared__ float sred[R_DIM];
    if (tid < R_DIM) sred[tid] = 0.0f;
    __syncthreads();
#pragma unroll
    for (int r = 0; r < R_DIM; r++) {
        float v = acc[r];
#pragma unroll
        for (int off = 16; off > 0; off >>= 1)
            v += __shfl_down_sync(0xffffffff, v, off);
        if ((tid & 31) == 0) atomicAdd(&sred[r], v);
    }
    __syncthreads();
    if (tid < R_DIM) g_shrunk[t * R_DIM + tid] = sred[tid];
}

// ---------------------------------------------------------------------------
// Kernel 4: HMMA (mma.sync bf16) GEMM with hi/lo split + fused LoRA epilogue
//   128x128x32 tiles, 4-stage cp.async pipeline, 8 warps, warp tile 64x32.
// ---------------------------------------------------------------------------
__global__ void __launch_bounds__(256) gemm_hmma(
    const float* __restrict__ bias, const float* __restrict__ lora_b,
    float* __restrict__ out) {
    extern __shared__ char dynsmem[];
    const uint32_t sbase = smem_u32(dynsmem);
    const int tid = threadIdx.x;
    const int wid = tid >> 5, lid = tid & 31;
    const int m0 = blockIdx.y * BM, n0 = blockIdx.x * BN;
    const int warp_m = wid & 1;        // 0..1 -> 64-row halves
    const int warp_n = wid >> 1;       // 0..3 -> 32-col quarters

    // ---------------- loader address precompute (8 x 16B per thread/stage) --
    const __nv_bfloat16* gsrc[8];
    uint32_t sdst[8];
    {
        const __nv_bfloat16* bases[4] = {
            g_Xhi + (size_t)m0 * H_DIM, g_Xlo + (size_t)m0 * H_DIM,
            g_Whi + (size_t)n0 * H_DIM, g_Wlo + (size_t)n0 * H_DIM};
#pragma unroll
        for (int i = 0; i < 8; i++) {
            int c = tid + 256 * i;
            int mat = c >> 9, w = c & 511, row = w >> 2, cq = w & 3;
            gsrc[i] = bases[mat] + (size_t)row * H_DIM + cq * 8;
            sdst[i] = mat * MAT_BYTES + swz((uint32_t)(row * 64 + cq * 16));
        }
    }

    // ---------------- prologue: fill STAGES-1 stages ----------------
#pragma unroll
    for (int s = 0; s < STAGES - 1; s++) {
        uint32_t sb = sbase + s * STAGE_BYTES;
#pragma unroll
        for (int i = 0; i < 8; i++) CP_ASYNC16(sb + sdst[i], gsrc[i] + s * BK);
        CP_COMMIT();
    }

    float acc[4][4][4];
#pragma unroll
    for (int a = 0; a < 4; a++)
#pragma unroll
        for (int b = 0; b < 4; b++)
#pragma unroll
            for (int c = 0; c < 4; c++) acc[a][b][c] = 0.0f;

    // per-thread ldmatrix row/col components
    const uint32_t a_row = warp_m * 64 + (lid & 15);
    const uint32_t a_kb  = ((lid >> 4) & 1) * 16;
    const uint32_t b_row = warp_n * 32 + ((lid >> 4) & 1) * 8 + (lid & 7);
    const uint32_t b_kb  = ((lid >> 3) & 1) * 16;

#pragma unroll 1
    for (int kt = 0; kt < KT_N; kt++) {
        CP_WAIT2();
        __syncthreads();
        // issue loads for tile kt+3 into slot (kt+3)&3 (safe: consumed at kt-1)
        const int nt = kt + STAGES - 1;
        if (nt < KT_N) {
            uint32_t sb = sbase + (nt & 3) * STAGE_BYTES;
#pragma unroll
            for (int i = 0; i < 8; i++) CP_ASYNC16(sb + sdst[i], gsrc[i] + nt * BK);
        }
        CP_COMMIT();

        const uint32_t st = sbase + (kt & 3) * STAGE_BYTES;
#pragma unroll
        for (int kk = 0; kk < 2; kk++) {
            const uint32_t koff = kk * 32;   // 16 bf16 = 32 bytes
            uint32_t ah[4][4], al[4][4], bh[2][4], bl[2][4];
#pragma unroll
            for (int mi = 0; mi < 4; mi++) {
                uint32_t o = swz((a_row + mi * 16) * 64 + koff + a_kb);
                LDSM4(ah[mi][0], ah[mi][1], ah[mi][2], ah[mi][3], st + o);
                LDSM4(al[mi][0], al[mi][1], al[mi][2], al[mi][3],
                      st + MAT_BYTES + o);
            }
#pragma unroll
            for (int nj2 = 0; nj2 < 2; nj2++) {
                uint32_t o = swz((b_row + nj2 * 16) * 64 + koff + b_kb);
                LDSM4(bh[nj2][0], bh[nj2][1], bh[nj2][2], bh[nj2][3],
                      st + 2 * MAT_BYTES + o);
                LDSM4(bl[nj2][0], bl[nj2][1], bl[nj2][2], bl[nj2][3],
                      st + 3 * MAT_BYTES + o);
            }
#pragma unroll
            for (int mi = 0; mi < 4; mi++)
#pragma unroll
                for (int nj = 0; nj < 4; nj++) {
                    const uint32_t bh0 = bh[nj >> 1][2 * (nj & 1)];
                    const uint32_t bh1 = bh[nj >> 1][2 * (nj & 1) + 1];
                    const uint32_t bl0 = bl[nj >> 1][2 * (nj & 1)];
                    const uint32_t bl1 = bl[nj >> 1][2 * (nj & 1) + 1];
                    mma16816(acc[mi][nj], ah[mi], bh0, bh1);   // hi*hi
                    mma16816(acc[mi][nj], ah[mi], bl0, bl1);   // hi*lo
                    mma16816(acc[mi][nj], al[mi], bh0, bh1);   // lo*hi
                }
        }
    }

    // ---------------- epilogue: bias + LoRA expand, write out ----------------
    const int l4 = lid >> 2, lq = lid & 3;
    const int colbase = n0 + warp_n * 32 + 2 * lq;
    float2 bia[4];
#pragma unroll
    for (int ni = 0; ni < 4; ni++) {
        bia[ni].x = __ldg(bias + colbase + ni * 8);
        bia[ni].y = __ldg(bias + colbase + ni * 8 + 1);
    }
#pragma unroll
    for (int mi = 0; mi < 4; mi++) {
#pragma unroll
        for (int h = 0; h < 2; h++) {
            const int row = m0 + warp_m * 64 + mi * 16 + h * 8 + l4;
            const int li = g_idx32[row];
            float s[R_DIM];
            if (li >= 0) {
                const float4* s4 = (const float4*)(g_shrunk + row * R_DIM);
#pragma unroll
                for (int q = 0; q < 4; q++) {
                    float4 v = s4[q];
                    s[q * 4 + 0] = v.x; s[q * 4 + 1] = v.y;
                    s[q * 4 + 2] = v.z; s[q * 4 + 3] = v.w;
                }
            }
            float* orow = out + (size_t)row * O_DIM;
#pragma unroll
            for (int ni = 0; ni < 4; ni++) {
                const int col = colbase + ni * 8;
                float v0 = acc[mi][ni][h * 2 + 0] + bia[ni].x;
                float v1 = acc[mi][ni][h * 2 + 1] + bia[ni].y;
                if (li >= 0) {
                    const float4* b4 =
                        (const float4*)(lora_b + ((size_t)li * O_DIM + col) * R_DIM);
                    float d0 = 0.0f, d1 = 0.0f;
#pragma unroll
                    for (int q = 0; q < 4; q++) {
                        float4 b0 = b4[q];
                        float4 b1 = b4[q + 4];
                        d0 += s[q * 4 + 0] * b0.x + s[q * 4 + 1] * b0.y +
                              s[q * 4 + 2] * b0.z + s[q * 4 + 3] * b0.w;
                        d1 += s[q * 4 + 0] * b1.x + s[q * 4 + 1] * b1.y +
                              s[q * 4 + 2] * b1.z + s[q * 4 + 3] * b1.w;
                    }
                    v0 += d0;
                    v1 += d1;
                }
                *(float2*)(orow + col) = make_float2(v0, v1);
            }
        }
    }
}

// ---------------------------------------------------------------------------
extern "C" void kernel_launch(void* const* d_in, const int* in_sizes, int n_in,
                              void* d_out, int out_size) {
    const float* x      = (const float*)d_in[0];  // (T, H)
    const float* weight = (const float*)d_in[1];  // (O, H)
    const float* bias   = (const float*)d_in[2];  // (O,)
    const float* lora_a = (const float*)d_in[3];  // (L, R, H)
    const float* lora_b = (const float*)d_in[4];  // (L, O, R)
    const int*   rawidx = (const int*)d_in[5];    // (T,) int32 or int64
    float* out = (float*)d_out;                   // (T, O)

    cudaFuncSetAttribute(gemm_hmma, cudaFuncAttributeMaxDynamicSharedMemorySize,
                         DYN_SMEM);

    prep_indices<<<1, 256>>>(rawidx);
    convert_x<<<(T_DIM * H_DIM / 4 + 255) / 256, 256>>>(x);
    convert_w<<<(O_DIM * H_DIM / 4 + 255) / 256, 256>>>(weight);
    shrunk_kernel<<<T_DIM, 256>>>(x, lora_a);
    dim3 grid(O_DIM / BN, T_DIM / BM);            // (32, 16)
    gemm_hmma<<<grid, 256, DYN_SMEM>>>(bias, lora_b, out);
}

// round 4
// speedup vs baseline: 2.6683x; 1.2181x over previous
#include <cuda_runtime.h>
#include <cuda_fp16.h>
#include <cstdint>

#define T_DIM 2048
#define H_DIM 4096
#define O_DIM 4096
#define L_DIM 32
#define R_DIM 16

#define BM 128
#define BN 128
#define BK 32
#define KT_N (H_DIM / BK)          // 128 k-tiles
#define STAGES 4
#define MAT_BYTES 8192             // 128 rows x 64 bytes (32 fp16)
#define STAGE_BYTES (3 * MAT_BYTES)
#define DYN_SMEM (STAGES * STAGE_BYTES)   // 96 KB

// ---------------- device scratch ----------------
__device__ int    g_idx32[T_DIM];
__device__ int    g_tok[T_DIM];
__device__ int    g_cnt[L_DIM];
__device__ int    g_base[L_DIM];
__device__ float  g_shrunk[T_DIM * R_DIM];
__device__ __half g_Xhi[T_DIM * H_DIM];
__device__ __half g_Xlo[T_DIM * H_DIM];
__device__ __half g_Whi[O_DIM * H_DIM];

// ---------------- helpers ----------------
__device__ __forceinline__ uint32_t smem_u32(const void* p) {
    uint32_t a;
    asm("{ .reg .u64 t; cvta.to.shared.u64 t, %1; cvt.u32.u64 %0, t; }"
        : "=r"(a) : "l"(p));
    return a;
}

__device__ __forceinline__ uint32_t swz(uint32_t o) {
    return o ^ ((o >> 3) & 0x30);   // 64B-row swizzle
}

#define CP_ASYNC16(dst, src) \
    asm volatile("cp.async.cg.shared.global [%0], [%1], 16;" :: "r"(dst), "l"(src))
#define CP_COMMIT() asm volatile("cp.async.commit_group;" ::: "memory")
#define CP_WAIT2()  asm volatile("cp.async.wait_group 2;" ::: "memory")

#define LDSM4(d0, d1, d2, d3, a)                                          \
    asm volatile("ldmatrix.sync.aligned.m8n8.x4.shared.b16 {%0,%1,%2,%3}, [%4];" \
                 : "=r"(d0), "=r"(d1), "=r"(d2), "=r"(d3) : "r"(a))

__device__ __forceinline__ void mma16816h(float* c, const uint32_t* a,
                                          uint32_t b0, uint32_t b1) {
    asm volatile(
        "mma.sync.aligned.m16n8k16.row.col.f32.f16.f16.f32 "
        "{%0,%1,%2,%3}, {%4,%5,%6,%7}, {%8,%9}, {%0,%1,%2,%3};"
        : "+f"(c[0]), "+f"(c[1]), "+f"(c[2]), "+f"(c[3])
        : "r"(a[0]), "r"(a[1]), "r"(a[2]), "r"(a[3]), "r"(b0), "r"(b1));
}

// ---------------------------------------------------------------------------
// Kernel 1: index decode (int64 vs int32) + zero shrunk + bucket tokens by
// adapter for the shrink kernel. Single block, 256 threads — trivial cost.
// ---------------------------------------------------------------------------
__global__ void bucket_kernel(const int* __restrict__ raw) {
    __shared__ int bad;
    __shared__ int s_cnt[L_DIM];
    __shared__ int s_base[L_DIM];
    const int tid = threadIdx.x;
    if (tid == 0) bad = 0;
    if (tid < L_DIM) s_cnt[tid] = 0;
    __syncthreads();
    {   // 256 pairs = 2048 bytes, in-bounds for either width
        int lo = raw[2 * tid], hi = raw[2 * tid + 1];
        bool ok = (hi == 0 && lo >= 0) || (hi == -1 && lo < 0);
        if (!ok) bad = 1;
    }
    __syncthreads();
    const bool is64 = (bad == 0);
    for (int t = tid; t < T_DIM; t += 256) {
        int v = is64 ? raw[2 * t] : raw[t];
        g_idx32[t] = v;
        if (v >= 0) atomicAdd(&s_cnt[v], 1);
    }
    for (int i = tid; i < T_DIM * R_DIM; i += 256) g_shrunk[i] = 0.0f;
    __syncthreads();
    if (tid == 0) {
        int a = 0;
        for (int l = 0; l < L_DIM; l++) { s_base[l] = a; a += s_cnt[l]; }
    }
    __syncthreads();
    if (tid < L_DIM) {
        g_cnt[tid] = s_cnt[tid];
        g_base[tid] = s_base[tid];
        s_cnt[tid] = 0;
    }
    __syncthreads();
    for (int t = tid; t < T_DIM; t += 256) {
        int v = g_idx32[t];
        if (v >= 0) {
            int p = atomicAdd(&s_cnt[v], 1);
            g_tok[s_base[v] + p] = t;
        }
    }
}

// ---------------------------------------------------------------------------
// Kernels 2a/2b: fp32 -> fp16 hi/lo conversions
// ---------------------------------------------------------------------------
__global__ void convert_x(const float* __restrict__ src) {
    int i = blockIdx.x * blockDim.x + threadIdx.x;
    if (i >= T_DIM * H_DIM / 4) return;
    float4 v = ((const float4*)src)[i];
    __half hx = __float2half(v.x), hy = __float2half(v.y);
    __half hz = __float2half(v.z), hw = __float2half(v.w);
    __half lx = __float2half(v.x - __half2float(hx));
    __half ly = __float2half(v.y - __half2float(hy));
    __half lz = __float2half(v.z - __half2float(hz));
    __half lw = __float2half(v.w - __half2float(hw));
    uint2 ph, pl;
    ph.x = ((uint32_t)__half_as_ushort(hy) << 16) | __half_as_ushort(hx);
    ph.y = ((uint32_t)__half_as_ushort(hw) << 16) | __half_as_ushort(hz);
    pl.x = ((uint32_t)__half_as_ushort(ly) << 16) | __half_as_ushort(lx);
    pl.y = ((uint32_t)__half_as_ushort(lw) << 16) | __half_as_ushort(lz);
    ((uint2*)g_Xhi)[i] = ph;
    ((uint2*)g_Xlo)[i] = pl;
}

__global__ void convert_w(const float* __restrict__ src) {
    int i = blockIdx.x * blockDim.x + threadIdx.x;
    if (i >= O_DIM * H_DIM / 4) return;
    float4 v = ((const float4*)src)[i];
    uint2 ph;
    ph.x = ((uint32_t)__half_as_ushort(__float2half(v.y)) << 16) |
           __half_as_ushort(__float2half(v.x));
    ph.y = ((uint32_t)__half_as_ushort(__float2half(v.w)) << 16) |
           __half_as_ushort(__float2half(v.z));
    ((uint2*)g_Whi)[i] = ph;
}

// ---------------------------------------------------------------------------
// Kernel 3: LoRA shrink, per-adapter: s[t,r] += sum_h x[t,h]*A[l,r,h]
//   grid (32 adapters, 4 H-chunks). A chunk (16 x 1024 fp32 = 64KB) in SMEM.
// ---------------------------------------------------------------------------
__global__ __launch_bounds__(256) void shrink2(
    const float* __restrict__ x, const float* __restrict__ lora_a) {
    extern __shared__ float sA[];          // 16 * 1024 floats
    const int l = blockIdx.x;
    const int n = g_cnt[l];
    if (n == 0) return;
    const int tid = threadIdx.x;
    const int wid = tid >> 5, lid = tid & 31;
    const int hb4 = blockIdx.y * 256;      // float4 units

    // load A[l][:, chunk] into smem
    const float4* a4 = ((const float4*)lora_a) + (size_t)l * R_DIM * (H_DIM / 4);
    float4* sA4 = (float4*)sA;
    for (int i = tid; i < R_DIM * 256; i += 256) {
        int r = i >> 8, j4 = i & 255;
        sA4[i] = a4[r * (H_DIM / 4) + hb4 + j4];
    }
    __syncthreads();

    const int base = g_base[l];
    for (int ti = wid; ti < n; ti += 8) {
        const int t = g_tok[base + ti];
        const float4* x4 = ((const float4*)x) + (size_t)t * (H_DIM / 4) + hb4;
        float4 xv[8];
#pragma unroll
        for (int j = 0; j < 8; j++) xv[j] = x4[lid + 32 * j];
        float acc[R_DIM];
#pragma unroll
        for (int r = 0; r < R_DIM; r++) acc[r] = 0.0f;
#pragma unroll
        for (int j = 0; j < 8; j++) {
#pragma unroll
            for (int r = 0; r < R_DIM; r++) {
                float4 av = sA4[r * 256 + lid + 32 * j];
                acc[r] += xv[j].x * av.x + xv[j].y * av.y +
                          xv[j].z * av.z + xv[j].w * av.w;
            }
        }
#pragma unroll
        for (int r = 0; r < R_DIM; r++) {
            float v = acc[r];
#pragma unroll
            for (int off = 16; off > 0; off >>= 1)
                v += __shfl_down_sync(0xffffffff, v, off);
            if (lid == 0) atomicAdd(&g_shrunk[t * R_DIM + r], v);
        }
    }
}

// ---------------------------------------------------------------------------
// Kernel 4: fp16 HMMA GEMM, 2-product hi/lo split + fused LoRA epilogue
//   acc += Xhi*Whi + Xlo*Whi.  128x128x32 tiles, 4-stage cp.async, 8 warps.
// ---------------------------------------------------------------------------
__global__ void __launch_bounds__(256) gemm_hmma(
    const float* __restrict__ bias, const float* __restrict__ lora_b,
    float* __restrict__ out) {
    extern __shared__ char dynsmem[];
    const uint32_t sbase = smem_u32(dynsmem);
    const int tid = threadIdx.x;
    const int wid = tid >> 5, lid = tid & 31;
    const int m0 = blockIdx.y * BM, n0 = blockIdx.x * BN;
    const int warp_m = wid & 1;        // 0..1 -> 64-row halves
    const int warp_n = wid >> 1;       // 0..3 -> 32-col quarters

    // loader precompute: 6 x 16B per thread per stage (3 matrices x 512 chunks)
    const __half* gsrc[6];
    uint32_t sdst[6];
    {
        const __half* bases[3] = {
            g_Xhi + (size_t)m0 * H_DIM, g_Xlo + (size_t)m0 * H_DIM,
            g_Whi + (size_t)n0 * H_DIM};
#pragma unroll
        for (int i = 0; i < 6; i++) {
            int c = tid + 256 * i;
            int mat = c >> 9, w = c & 511, row = w >> 2, cq = w & 3;
            gsrc[i] = bases[mat] + (size_t)row * H_DIM + cq * 8;
            sdst[i] = mat * MAT_BYTES + swz((uint32_t)(row * 64 + cq * 16));
        }
    }

#pragma unroll
    for (int s = 0; s < STAGES - 1; s++) {
        uint32_t sb = sbase + s * STAGE_BYTES;
#pragma unroll
        for (int i = 0; i < 6; i++) CP_ASYNC16(sb + sdst[i], gsrc[i] + s * BK);
        CP_COMMIT();
    }

    float acc[4][4][4];
#pragma unroll
    for (int a = 0; a < 4; a++)
#pragma unroll
        for (int b = 0; b < 4; b++)
#pragma unroll
            for (int c = 0; c < 4; c++) acc[a][b][c] = 0.0f;

    const uint32_t a_row = warp_m * 64 + (lid & 15);
    const uint32_t a_kb  = ((lid >> 4) & 1) * 16;
    const uint32_t b_row = warp_n * 32 + ((lid >> 4) & 1) * 8 + (lid & 7);
    const uint32_t b_kb  = ((lid >> 3) & 1) * 16;

#pragma unroll 1
    for (int kt = 0; kt < KT_N; kt++) {
        CP_WAIT2();
        __syncthreads();
        const int nt = kt + STAGES - 1;
        if (nt < KT_N) {
            uint32_t sb = sbase + (nt & 3) * STAGE_BYTES;
#pragma unroll
            for (int i = 0; i < 6; i++) CP_ASYNC16(sb + sdst[i], gsrc[i] + nt * BK);
        }
        CP_COMMIT();

        const uint32_t st = sbase + (kt & 3) * STAGE_BYTES;
#pragma unroll
        for (int kk = 0; kk < 2; kk++) {
            const uint32_t koff = kk * 32;   // 16 fp16 = 32 bytes
            uint32_t ah[4][4], al[4][4], bh[2][4];
#pragma unroll
            for (int mi = 0; mi < 4; mi++) {
                uint32_t o = swz((a_row + mi * 16) * 64 + koff + a_kb);
                LDSM4(ah[mi][0], ah[mi][1], ah[mi][2], ah[mi][3], st + o);
                LDSM4(al[mi][0], al[mi][1], al[mi][2], al[mi][3],
                      st + MAT_BYTES + o);
            }
#pragma unroll
            for (int nj2 = 0; nj2 < 2; nj2++) {
                uint32_t o = swz((b_row + nj2 * 16) * 64 + koff + b_kb);
                LDSM4(bh[nj2][0], bh[nj2][1], bh[nj2][2], bh[nj2][3],
                      st + 2 * MAT_BYTES + o);
            }
#pragma unroll
            for (int mi = 0; mi < 4; mi++)
#pragma unroll
                for (int nj = 0; nj < 4; nj++) {
                    const uint32_t b0 = bh[nj >> 1][2 * (nj & 1)];
                    const uint32_t b1 = bh[nj >> 1][2 * (nj & 1) + 1];
                    mma16816h(acc[mi][nj], ah[mi], b0, b1);   // hi*hi
                    mma16816h(acc[mi][nj], al[mi], b0, b1);   // lo*hi
                }
        }
    }

    // ---------------- epilogue: bias + LoRA expand ----------------
    const int l4 = lid >> 2, lq = lid & 3;
    const int colbase = n0 + warp_n * 32 + 2 * lq;
    float2 bia[4];
#pragma unroll
    for (int ni = 0; ni < 4; ni++) {
        bia[ni].x = __ldg(bias + colbase + ni * 8);
        bia[ni].y = __ldg(bias + colbase + ni * 8 + 1);
    }
#pragma unroll
    for (int mi = 0; mi < 4; mi++) {
#pragma unroll
        for (int h = 0; h < 2; h++) {
            const int row = m0 + warp_m * 64 + mi * 16 + h * 8 + l4;
            const int li = g_idx32[row];
            float s[R_DIM];
            if (li >= 0) {
                const float4* s4 = (const float4*)(g_shrunk + row * R_DIM);
#pragma unroll
                for (int q = 0; q < 4; q++) {
                    float4 v = s4[q];
                    s[q * 4 + 0] = v.x; s[q * 4 + 1] = v.y;
                    s[q * 4 + 2] = v.z; s[q * 4 + 3] = v.w;
                }
            }
            float* orow = out + (size_t)row * O_DIM;
#pragma unroll
            for (int ni = 0; ni < 4; ni++) {
                const int col = colbase + ni * 8;
                float v0 = acc[mi][ni][h * 2 + 0] + bia[ni].x;
                float v1 = acc[mi][ni][h * 2 + 1] + bia[ni].y;
                if (li >= 0) {
                    const float4* b4 =
                        (const float4*)(lora_b + ((size_t)li * O_DIM + col) * R_DIM);
                    float d0 = 0.0f, d1 = 0.0f;
#pragma unroll
                    for (int q = 0; q < 4; q++) {
                        float4 bb0 = b4[q];
                        float4 bb1 = b4[q + 4];
                        d0 += s[q * 4 + 0] * bb0.x + s[q * 4 + 1] * bb0.y +
                              s[q * 4 + 2] * bb0.z + s[q * 4 + 3] * bb0.w;
                        d1 += s[q * 4 + 0] * bb1.x + s[q * 4 + 1] * bb1.y +
                              s[q * 4 + 2] * bb1.z + s[q * 4 + 3] * bb1.w;
                    }
                    v0 += d0;
                    v1 += d1;
                }
                *(float2*)(orow + col) = make_float2(v0, v1);
            }
        }
    }
}

// ---------------------------------------------------------------------------
extern "C" void kernel_launch(void* const* d_in, const int* in_sizes, int n_in,
                              void* d_out, int out_size) {
    const float* x      = (const float*)d_in[0];  // (T, H)
    const float* weight = (const float*)d_in[1];  // (O, H)
    const float* bias   = (const float*)d_in[2];  // (O,)
    const float* lora_a = (const float*)d_in[3];  // (L, R, H)
    const float* lora_b = (const float*)d_in[4];  // (L, O, R)
    const int*   rawidx = (const int*)d_in[5];    // (T,) int32 or int64
    float* out = (float*)d_out;                   // (T, O)

    cudaFuncSetAttribute(gemm_hmma, cudaFuncAttributeMaxDynamicSharedMemorySize,
                         DYN_SMEM);
    cudaFuncSetAttribute(shrink2, cudaFuncAttributeMaxDynamicSharedMemorySize,
                         R_DIM * 1024 * sizeof(float));

    bucket_kernel<<<1, 256>>>(rawidx);
    convert_x<<<(T_DIM * H_DIM / 4 + 255) / 256, 256>>>(x);
    convert_w<<<(O_DIM * H_DIM / 4 + 255) / 256, 256>>>(weight);
    shrink2<<<dim3(L_DIM, 4), 256, R_DIM * 1024 * sizeof(float)>>>(x, lora_a);
    dim3 grid(O_DIM / BN, T_DIM / BM);            // (32, 16)
    gemm_hmma<<<grid, 256, DYN_SMEM>>>(bias, lora_b, out);
}

// round 5
// speedup vs baseline: 3.3291x; 1.2476x over previous
#include <cuda_runtime.h>
#include <cuda_fp16.h>
#include <cstdint>

#define T_DIM 2048
#define H_DIM 4096
#define O_DIM 4096
#define L_DIM 32
#define R_DIM 16

#define BM 128
#define BN 128
#define BK 32
#define KT_N (H_DIM / BK)          // 128 k-tiles
#define STAGES 4
#define MAT_BYTES 8192             // 128 rows x 64 bytes (32 fp16)
#define STAGE_BYTES (3 * MAT_BYTES)
#define DYN_SMEM (STAGES * STAGE_BYTES)   // 96 KB

#define SH_CH 8                    // shrink H-chunks
#define CHUNK4 (H_DIM / 4 / SH_CH) // 128 float4 per chunk

// ---------------- device scratch ----------------
__device__ int    g_idx32[T_DIM];
__device__ int    g_tok[T_DIM];
__device__ int    g_cnt[L_DIM];
__device__ int    g_base[L_DIM];
__device__ float  g_shrunk[T_DIM * R_DIM];
__device__ __half g_Xhi[T_DIM * H_DIM];
__device__ __half g_Xlo[T_DIM * H_DIM];
__device__ __half g_Whi[O_DIM * H_DIM];

// ---------------- helpers ----------------
__device__ __forceinline__ uint32_t smem_u32(const void* p) {
    uint32_t a;
    asm("{ .reg .u64 t; cvta.to.shared.u64 t, %1; cvt.u32.u64 %0, t; }"
        : "=r"(a) : "l"(p));
    return a;
}

__device__ __forceinline__ uint32_t swz(uint32_t o) {
    return o ^ ((o >> 3) & 0x30);   // 64B-row swizzle
}

#define CP_ASYNC16(dst, src) \
    asm volatile("cp.async.cg.shared.global [%0], [%1], 16;" :: "r"(dst), "l"(src))
#define CP_COMMIT() asm volatile("cp.async.commit_group;" ::: "memory")
#define CP_WAIT2()  asm volatile("cp.async.wait_group 2;" ::: "memory")

#define LDSM4(d0, d1, d2, d3, a)                                          \
    asm volatile("ldmatrix.sync.aligned.m8n8.x4.shared.b16 {%0,%1,%2,%3}, [%4];" \
                 : "=r"(d0), "=r"(d1), "=r"(d2), "=r"(d3) : "r"(a))

__device__ __forceinline__ void mma16816h(float* c, const uint32_t* a,
                                          uint32_t b0, uint32_t b1) {
    asm volatile(
        "mma.sync.aligned.m16n8k16.row.col.f32.f16.f16.f32 "
        "{%0,%1,%2,%3}, {%4,%5,%6,%7}, {%8,%9}, {%0,%1,%2,%3};"
        : "+f"(c[0]), "+f"(c[1]), "+f"(c[2]), "+f"(c[3])
        : "r"(a[0]), "r"(a[1]), "r"(a[2]), "r"(a[3]), "r"(b0), "r"(b1));
}

// ---------------------------------------------------------------------------
// Kernel 1: index decode (int64 vs int32) + bucket tokens by adapter.
// ---------------------------------------------------------------------------
__global__ void bucket_kernel(const int* __restrict__ raw) {
    __shared__ int bad;
    __shared__ int s_cnt[L_DIM];
    __shared__ int s_base[L_DIM];
    const int tid = threadIdx.x;
    if (tid == 0) bad = 0;
    if (tid < L_DIM) s_cnt[tid] = 0;
    __syncthreads();
    {   // 256 pairs = 2048 bytes, in-bounds for either width
        int lo = raw[2 * tid], hi = raw[2 * tid + 1];
        bool ok = (hi == 0 && lo >= 0) || (hi == -1 && lo < 0);
        if (!ok) bad = 1;
    }
    __syncthreads();
    const bool is64 = (bad == 0);
    for (int t = tid; t < T_DIM; t += 256) {
        int v = is64 ? raw[2 * t] : raw[t];
        g_idx32[t] = v;
        if (v >= 0) atomicAdd(&s_cnt[v], 1);
    }
    __syncthreads();
    if (tid == 0) {
        int a = 0;
        for (int l = 0; l < L_DIM; l++) { s_base[l] = a; a += s_cnt[l]; }
    }
    __syncthreads();
    if (tid < L_DIM) {
        g_cnt[tid] = s_cnt[tid];
        g_base[tid] = s_base[tid];
        s_cnt[tid] = 0;
    }
    __syncthreads();
    for (int t = tid; t < T_DIM; t += 256) {
        int v = g_idx32[t];
        if (v >= 0) {
            int p = atomicAdd(&s_cnt[v], 1);
            g_tok[s_base[v] + p] = t;
        }
    }
}

// ---------------------------------------------------------------------------
// Kernel 2a: fp32 -> fp16 hi/lo split of X  (+ zero g_shrunk in first blocks)
// ---------------------------------------------------------------------------
__global__ void convert_x(const float* __restrict__ src) {
    int i = blockIdx.x * blockDim.x + threadIdx.x;
    if (i < T_DIM * R_DIM / 4) ((float4*)g_shrunk)[i] = make_float4(0, 0, 0, 0);
    if (i >= T_DIM * H_DIM / 4) return;
    float4 v = ((const float4*)src)[i];
    __half hx = __float2half(v.x), hy = __float2half(v.y);
    __half hz = __float2half(v.z), hw = __float2half(v.w);
    __half lx = __float2half(v.x - __half2float(hx));
    __half ly = __float2half(v.y - __half2float(hy));
    __half lz = __float2half(v.z - __half2float(hz));
    __half lw = __float2half(v.w - __half2float(hw));
    uint2 ph, pl;
    ph.x = ((uint32_t)__half_as_ushort(hy) << 16) | __half_as_ushort(hx);
    ph.y = ((uint32_t)__half_as_ushort(hw) << 16) | __half_as_ushort(hz);
    pl.x = ((uint32_t)__half_as_ushort(ly) << 16) | __half_as_ushort(lx);
    pl.y = ((uint32_t)__half_as_ushort(lw) << 16) | __half_as_ushort(lz);
    ((uint2*)g_Xhi)[i] = ph;
    ((uint2*)g_Xlo)[i] = pl;
}

// ---------------------------------------------------------------------------
// Kernel 2b: fp32 -> fp16 of W (hi only)
// ---------------------------------------------------------------------------
__global__ void convert_w(const float* __restrict__ src) {
    int i = blockIdx.x * blockDim.x + threadIdx.x;
    if (i >= O_DIM * H_DIM / 4) return;
    float4 v = ((const float4*)src)[i];
    uint2 ph;
    ph.x = ((uint32_t)__half_as_ushort(__float2half(v.y)) << 16) |
           __half_as_ushort(__float2half(v.x));
    ph.y = ((uint32_t)__half_as_ushort(__float2half(v.w)) << 16) |
           __half_as_ushort(__float2half(v.z));
    ((uint2*)g_Whi)[i] = ph;
}

// ---------------------------------------------------------------------------
// Kernel 3: LoRA shrink, grid (32 adapters, 8 H-chunks), 256 thr, A in SMEM.
// ---------------------------------------------------------------------------
__global__ __launch_bounds__(256) void shrink2(
    const float* __restrict__ x, const float* __restrict__ lora_a) {
    __shared__ float4 sA4[R_DIM * CHUNK4];       // 16 x 128 float4 = 32 KB
    const int l = blockIdx.x;
    const int n = g_cnt[l];
    if (n == 0) return;
    const int tid = threadIdx.x;
    const int wid = tid >> 5, lid = tid & 31;
    const int hb4 = blockIdx.y * CHUNK4;

    const float4* a4 = ((const float4*)lora_a) + (size_t)l * R_DIM * (H_DIM / 4);
    for (int i = tid; i < R_DIM * CHUNK4; i += 256) {
        int r = i / CHUNK4, j4 = i % CHUNK4;
        sA4[i] = a4[r * (H_DIM / 4) + hb4 + j4];
    }
    __syncthreads();

    const int base = g_base[l];
    for (int ti = wid; ti < n; ti += 8) {
        const int t = g_tok[base + ti];
        const float4* x4 = ((const float4*)x) + (size_t)t * (H_DIM / 4) + hb4;
        float4 xv[4];
#pragma unroll
        for (int j = 0; j < 4; j++) xv[j] = x4[lid + 32 * j];
        float acc[R_DIM];
#pragma unroll
        for (int r = 0; r < R_DIM; r++) acc[r] = 0.0f;
#pragma unroll
        for (int j = 0; j < 4; j++) {
#pragma unroll
            for (int r = 0; r < R_DIM; r++) {
                float4 av = sA4[r * CHUNK4 + lid + 32 * j];
                acc[r] += xv[j].x * av.x + xv[j].y * av.y +
                          xv[j].z * av.z + xv[j].w * av.w;
            }
        }
#pragma unroll
        for (int r = 0; r < R_DIM; r++) {
            float v = acc[r];
#pragma unroll
            for (int off = 16; off > 0; off >>= 1)
                v += __shfl_down_sync(0xffffffff, v, off);
            if (lid == 0) atomicAdd(&g_shrunk[t * R_DIM + r], v);
        }
    }
}

// ---------------------------------------------------------------------------
// Kernel 4: fp16 HMMA GEMM, 2-product hi/lo split + fused LoRA epilogue
//   128x128x32 tiles, 4-stage cp.async, 8 warps, OCCUPANCY 2 (regs <= 128).
// ---------------------------------------------------------------------------
__global__ void __launch_bounds__(256, 2) gemm_hmma(
    const float* __restrict__ bias, const float* __restrict__ lora_b,
    float* __restrict__ out) {
    extern __shared__ char dynsmem[];
    const uint32_t sbase = smem_u32(dynsmem);
    const int tid = threadIdx.x;
    const int wid = tid >> 5, lid = tid & 31;
    const int m0 = blockIdx.y * BM, n0 = blockIdx.x * BN;
    const int warp_m = wid & 1;        // 0..1 -> 64-row halves
    const int warp_n = wid >> 1;       // 0..3 -> 32-col quarters

    // loader precompute: 6 x 16B per thread per stage (3 matrices x 512 chunks)
    const __half* gsrc[6];
    uint32_t sdst[6];
    {
        const __half* bases[3] = {
            g_Xhi + (size_t)m0 * H_DIM, g_Xlo + (size_t)m0 * H_DIM,
            g_Whi + (size_t)n0 * H_DIM};
#pragma unroll
        for (int i = 0; i < 6; i++) {
            int c = tid + 256 * i;
            int mat = c >> 9, w = c & 511, row = w >> 2, cq = w & 3;
            gsrc[i] = bases[mat] + (size_t)row * H_DIM + cq * 8;
            sdst[i] = mat * MAT_BYTES + swz((uint32_t)(row * 64 + cq * 16));
        }
    }

#pragma unroll
    for (int s = 0; s < STAGES - 1; s++) {
        uint32_t sb = sbase + s * STAGE_BYTES;
#pragma unroll
        for (int i = 0; i < 6; i++) CP_ASYNC16(sb + sdst[i], gsrc[i] + s * BK);
        CP_COMMIT();
    }

    float acc[4][4][4];
#pragma unroll
    for (int a = 0; a < 4; a++)
#pragma unroll
        for (int b = 0; b < 4; b++)
#pragma unroll
            for (int c = 0; c < 4; c++) acc[a][b][c] = 0.0f;

    const uint32_t a_row = warp_m * 64 + (lid & 15);
    const uint32_t a_kb  = ((lid >> 4) & 1) * 16;
    const uint32_t b_row = warp_n * 32 + ((lid >> 4) & 1) * 8 + (lid & 7);
    const uint32_t b_kb  = ((lid >> 3) & 1) * 16;

#pragma unroll 1
    for (int kt = 0; kt < KT_N; kt++) {
        CP_WAIT2();
        __syncthreads();
        const int nt = kt + STAGES - 1;
        if (nt < KT_N) {
            uint32_t sb = sbase + (nt & 3) * STAGE_BYTES;
#pragma unroll
            for (int i = 0; i < 6; i++) CP_ASYNC16(sb + sdst[i], gsrc[i] + nt * BK);
        }
        CP_COMMIT();

        const uint32_t st = sbase + (kt & 3) * STAGE_BYTES;
#pragma unroll
        for (int kk = 0; kk < 2; kk++) {
            const uint32_t koff = kk * 32;   // 16 fp16 = 32 bytes
            uint32_t bh[2][4];
#pragma unroll
            for (int nj2 = 0; nj2 < 2; nj2++) {
                uint32_t o = swz((b_row + nj2 * 16) * 64 + koff + b_kb);
                LDSM4(bh[nj2][0], bh[nj2][1], bh[nj2][2], bh[nj2][3],
                      st + 2 * MAT_BYTES + o);
            }
            // A fragments kept transient (per-mi) to stay under 128 regs
#pragma unroll
            for (int mi = 0; mi < 4; mi++) {
                uint32_t ah[4], al[4];
                uint32_t o = swz((a_row + mi * 16) * 64 + koff + a_kb);
                LDSM4(ah[0], ah[1], ah[2], ah[3], st + o);
                LDSM4(al[0], al[1], al[2], al[3], st + MAT_BYTES + o);
#pragma unroll
                for (int nj = 0; nj < 4; nj++) {
                    const uint32_t b0 = bh[nj >> 1][2 * (nj & 1)];
                    const uint32_t b1 = bh[nj >> 1][2 * (nj & 1) + 1];
                    mma16816h(acc[mi][nj], ah, b0, b1);   // hi*hi
                    mma16816h(acc[mi][nj], al, b0, b1);   // lo*hi
                }
            }
        }
    }

    // ---------------- epilogue: bias + LoRA expand ----------------
    const int l4 = lid >> 2, lq = lid & 3;
    const int colbase = n0 + warp_n * 32 + 2 * lq;
    float2 bia[4];
#pragma unroll
    for (int ni = 0; ni < 4; ni++) {
        bia[ni].x = __ldg(bias + colbase + ni * 8);
        bia[ni].y = __ldg(bias + colbase + ni * 8 + 1);
    }
#pragma unroll
    for (int mi = 0; mi < 4; mi++) {
#pragma unroll
        for (int h = 0; h < 2; h++) {
            const int row = m0 + warp_m * 64 + mi * 16 + h * 8 + l4;
            const int li = g_idx32[row];
            float s[R_DIM];
            if (li >= 0) {
                const float4* s4 = (const float4*)(g_shrunk + row * R_DIM);
#pragma unroll
                for (int q = 0; q < 4; q++) {
                    float4 v = s4[q];
                    s[q * 4 + 0] = v.x; s[q * 4 + 1] = v.y;
                    s[q * 4 + 2] = v.z; s[q * 4 + 3] = v.w;
                }
            }
            float* orow = out + (size_t)row * O_DIM;
#pragma unroll
            for (int ni = 0; ni < 4; ni++) {
                const int col = colbase + ni * 8;
                float v0 = acc[mi][ni][h * 2 + 0] + bia[ni].x;
                float v1 = acc[mi][ni][h * 2 + 1] + bia[ni].y;
                if (li >= 0) {
                    const float4* b4 =
                        (const float4*)(lora_b + ((size_t)li * O_DIM + col) * R_DIM);
                    float d0 = 0.0f, d1 = 0.0f;
#pragma unroll
                    for (int q = 0; q < 4; q++) {
                        float4 bb0 = b4[q];
                        float4 bb1 = b4[q + 4];
                        d0 += s[q * 4 + 0] * bb0.x + s[q * 4 + 1] * bb0.y +
                              s[q * 4 + 2] * bb0.z + s[q * 4 + 3] * bb0.w;
                        d1 += s[q * 4 + 0] * bb1.x + s[q * 4 + 1] * bb1.y +
                              s[q * 4 + 2] * bb1.z + s[q * 4 + 3] * bb1.w;
                    }
                    v0 += d0;
                    v1 += d1;
                }
                *(float2*)(orow + col) = make_float2(v0, v1);
            }
        }
    }
}

// ---------------------------------------------------------------------------
extern "C" void kernel_launch(void* const* d_in, const int* in_sizes, int n_in,
                              void* d_out, int out_size) {
    const float* x      = (const float*)d_in[0];  // (T, H)
    const float* weight = (const float*)d_in[1];  // (O, H)
    const float* bias   = (const float*)d_in[2];  // (O,)
    const float* lora_a = (const float*)d_in[3];  // (L, R, H)
    const float* lora_b = (const float*)d_in[4];  // (L, O, R)
    const int*   rawidx = (const int*)d_in[5];    // (T,) int32 or int64
    float* out = (float*)d_out;                   // (T, O)

    cudaFuncSetAttribute(gemm_hmma, cudaFuncAttributeMaxDynamicSharedMemorySize,
                         DYN_SMEM);

    bucket_kernel<<<1, 256>>>(rawidx);
    convert_x<<<(T_DIM * H_DIM / 4 + 255) / 256, 256>>>(x);
    convert_w<<<(O_DIM * H_DIM / 4 + 255) / 256, 256>>>(weight);
    shrink2<<<dim3(L_DIM, SH_CH), 256>>>(x, lora_a);
    dim3 grid(O_DIM / BN, T_DIM / BM);            // (32, 16)
    gemm_hmma<<<grid, 256, DYN_SMEM>>>(bias, lora_b, out);
}

// round 6
// speedup vs baseline: 3.5019x; 1.0519x over previous
#include <cuda_runtime.h>
#include <cuda_fp16.h>
#include <cstdint>

#define T_DIM 2048
#define H_DIM 4096
#define O_DIM 4096
#define L_DIM 32
#define R_DIM 16

#define BM 128
#define BN 128
#define BK 32
#define KT_N (H_DIM / BK)          // 128 k-tiles
#define STAGES 4
#define MAT_BYTES 8192             // 128 rows x 64 bytes (32 fp16)
#define STAGE_BYTES (3 * MAT_BYTES)
#define DYN_SMEM (STAGES * STAGE_BYTES)   // 96 KB

#define SH_CH 8                    // shrink H-chunks
#define SH_Z 4                     // shrink token-split
#define CHUNK4 (H_DIM / 4 / SH_CH) // 128 float4 per chunk

// ---------------- device scratch ----------------
__device__ int    g_idx32[T_DIM];
__device__ int    g_tok[T_DIM];
__device__ int    g_cnt[L_DIM];
__device__ int    g_base[L_DIM];
__device__ float  g_shrunk[T_DIM * R_DIM];
__device__ __half g_Xhi[T_DIM * H_DIM];
__device__ __half g_Xlo[T_DIM * H_DIM];
__device__ __half g_Whi[O_DIM * H_DIM];

// ---------------- helpers ----------------
__device__ __forceinline__ uint32_t smem_u32(const void* p) {
    uint32_t a;
    asm("{ .reg .u64 t; cvta.to.shared.u64 t, %1; cvt.u32.u64 %0, t; }"
        : "=r"(a) : "l"(p));
    return a;
}

__device__ __forceinline__ uint32_t swz(uint32_t o) {
    return o ^ ((o >> 3) & 0x30);   // 64B-row swizzle
}

#define CP_ASYNC16(dst, src) \
    asm volatile("cp.async.cg.shared.global [%0], [%1], 16;" :: "r"(dst), "l"(src))
#define CP_COMMIT() asm volatile("cp.async.commit_group;" ::: "memory")
#define CP_WAIT2()  asm volatile("cp.async.wait_group 2;" ::: "memory")

#define LDSM4(d0, d1, d2, d3, a)                                          \
    asm volatile("ldmatrix.sync.aligned.m8n8.x4.shared.b16 {%0,%1,%2,%3}, [%4];" \
                 : "=r"(d0), "=r"(d1), "=r"(d2), "=r"(d3) : "r"(a))

__device__ __forceinline__ void mma16816h(float* c, const uint32_t* a,
                                          uint32_t b0, uint32_t b1) {
    asm volatile(
        "mma.sync.aligned.m16n8k16.row.col.f32.f16.f16.f32 "
        "{%0,%1,%2,%3}, {%4,%5,%6,%7}, {%8,%9}, {%0,%1,%2,%3};"
        : "+f"(c[0]), "+f"(c[1]), "+f"(c[2]), "+f"(c[3])
        : "r"(a[0]), "r"(a[1]), "r"(a[2]), "r"(a[3]), "r"(b0), "r"(b1));
}

// ---------------------------------------------------------------------------
// Kernel 1: index decode (int64 vs int32) + bucket tokens + zero g_shrunk.
// ---------------------------------------------------------------------------
__global__ void bucket_kernel(const int* __restrict__ raw) {
    __shared__ int bad;
    __shared__ int s_cnt[L_DIM];
    __shared__ int s_base[L_DIM];
    const int tid = threadIdx.x;
    if (tid == 0) bad = 0;
    if (tid < L_DIM) s_cnt[tid] = 0;
    __syncthreads();
    {   // 256 pairs = 2048 bytes, in-bounds for either width
        int lo = raw[2 * tid], hi = raw[2 * tid + 1];
        bool ok = (hi == 0 && lo >= 0) || (hi == -1 && lo < 0);
        if (!ok) bad = 1;
    }
    __syncthreads();
    const bool is64 = (bad == 0);
    for (int t = tid; t < T_DIM; t += 256) {
        int v = is64 ? raw[2 * t] : raw[t];
        g_idx32[t] = v;
        if (v >= 0) atomicAdd(&s_cnt[v], 1);
    }
    for (int i = tid; i < T_DIM * R_DIM / 4; i += 256)
        ((float4*)g_shrunk)[i] = make_float4(0, 0, 0, 0);
    __syncthreads();
    if (tid == 0) {
        int a = 0;
        for (int l = 0; l < L_DIM; l++) { s_base[l] = a; a += s_cnt[l]; }
    }
    __syncthreads();
    if (tid < L_DIM) {
        g_cnt[tid] = s_cnt[tid];
        g_base[tid] = s_base[tid];
        s_cnt[tid] = 0;
    }
    __syncthreads();
    for (int t = tid; t < T_DIM; t += 256) {
        int v = g_idx32[t];
        if (v >= 0) {
            int p = atomicAdd(&s_cnt[v], 1);
            g_tok[s_base[v] + p] = t;
        }
    }
}

// ---------------------------------------------------------------------------
// Kernel 2a: fp32 -> fp16 hi/lo split of X
// ---------------------------------------------------------------------------
__global__ void convert_x(const float* __restrict__ src) {
    int i = blockIdx.x * blockDim.x + threadIdx.x;
    if (i >= T_DIM * H_DIM / 4) return;
    float4 v = ((const float4*)src)[i];
    __half hx = __float2half(v.x), hy = __float2half(v.y);
    __half hz = __float2half(v.z), hw = __float2half(v.w);
    __half lx = __float2half(v.x - __half2float(hx));
    __half ly = __float2half(v.y - __half2float(hy));
    __half lz = __float2half(v.z - __half2float(hz));
    __half lw = __float2half(v.w - __half2float(hw));
    uint2 ph, pl;
    ph.x = ((uint32_t)__half_as_ushort(hy) << 16) | __half_as_ushort(hx);
    ph.y = ((uint32_t)__half_as_ushort(hw) << 16) | __half_as_ushort(hz);
    pl.x = ((uint32_t)__half_as_ushort(ly) << 16) | __half_as_ushort(lx);
    pl.y = ((uint32_t)__half_as_ushort(lw) << 16) | __half_as_ushort(lz);
    ((uint2*)g_Xhi)[i] = ph;
    ((uint2*)g_Xlo)[i] = pl;
}

// ---------------------------------------------------------------------------
// Kernel 2b: fp32 -> fp16 of W (hi only)
// ---------------------------------------------------------------------------
__global__ void convert_w(const float* __restrict__ src) {
    int i = blockIdx.x * blockDim.x + threadIdx.x;
    if (i >= O_DIM * H_DIM / 4) return;
    float4 v = ((const float4*)src)[i];
    uint2 ph;
    ph.x = ((uint32_t)__half_as_ushort(__float2half(v.y)) << 16) |
           __half_as_ushort(__float2half(v.x));
    ph.y = ((uint32_t)__half_as_ushort(__float2half(v.w)) << 16) |
           __half_as_ushort(__float2half(v.z));
    ((uint2*)g_Whi)[i] = ph;
}

// ---------------------------------------------------------------------------
// Kernel 3: LoRA shrink, grid (32 adapters, 8 H-chunks, 4 token-slices),
//   256 thr, A-chunk in SMEM, warp-slot strides 32 tokens.
// ---------------------------------------------------------------------------
__global__ __launch_bounds__(256) void shrink3(
    const float* __restrict__ x, const float* __restrict__ lora_a) {
    __shared__ float4 sA4[R_DIM * CHUNK4];       // 16 x 128 float4 = 32 KB
    const int l = blockIdx.x;
    const int n = g_cnt[l];
    if (n == 0) return;
    const int tid = threadIdx.x;
    const int wid = tid >> 5, lid = tid & 31;
    const int slot = blockIdx.z * 8 + wid;       // 0..31
    if (blockIdx.z * 8 >= n) return;             // whole block idle -> skip
    const int hb4 = blockIdx.y * CHUNK4;

    const float4* a4 = ((const float4*)lora_a) + (size_t)l * R_DIM * (H_DIM / 4);
    for (int i = tid; i < R_DIM * CHUNK4; i += 256) {
        int r = i / CHUNK4, j4 = i % CHUNK4;
        sA4[i] = a4[r * (H_DIM / 4) + hb4 + j4];
    }
    __syncthreads();

    const int base = g_base[l];
    for (int ti = slot; ti < n; ti += 32) {
        const int t = g_tok[base + ti];
        const float4* x4 = ((const float4*)x) + (size_t)t * (H_DIM / 4) + hb4;
        float4 xv[4];
#pragma unroll
        for (int j = 0; j < 4; j++) xv[j] = x4[lid + 32 * j];
        float acc[R_DIM];
#pragma unroll
        for (int r = 0; r < R_DIM; r++) acc[r] = 0.0f;
#pragma unroll
        for (int j = 0; j < 4; j++) {
#pragma unroll
            for (int r = 0; r < R_DIM; r++) {
                float4 av = sA4[r * CHUNK4 + lid + 32 * j];
                acc[r] += xv[j].x * av.x + xv[j].y * av.y +
                          xv[j].z * av.z + xv[j].w * av.w;
            }
        }
#pragma unroll
        for (int r = 0; r < R_DIM; r++) {
            float v = acc[r];
#pragma unroll
            for (int off = 16; off > 0; off >>= 1)
                v += __shfl_down_sync(0xffffffff, v, off);
            if (lid == 0) atomicAdd(&g_shrunk[t * R_DIM + r], v);
        }
    }
}

// ---------------------------------------------------------------------------
// Kernel 4: fp16 HMMA GEMM, 2-product hi/lo split + fused LoRA epilogue
//   128x128x32 tiles, 4-stage cp.async, 8 warps, occupancy 2. (unchanged R5)
// ---------------------------------------------------------------------------
__global__ void __launch_bounds__(256, 2) gemm_hmma(
    const float* __restrict__ bias, const float* __restrict__ lora_b,
    float* __restrict__ out) {
    extern __shared__ char dynsmem[];
    const uint32_t sbase = smem_u32(dynsmem);
    const int tid = threadIdx.x;
    const int wid = tid >> 5, lid = tid & 31;
    const int m0 = blockIdx.y * BM, n0 = blockIdx.x * BN;
    const int warp_m = wid & 1;
    const int warp_n = wid >> 1;

    const __half* gsrc[6];
    uint32_t sdst[6];
    {
        const __half* bases[3] = {
            g_Xhi + (size_t)m0 * H_DIM, g_Xlo + (size_t)m0 * H_DIM,
            g_Whi + (size_t)n0 * H_DIM};
#pragma unroll
        for (int i = 0; i < 6; i++) {
            int c = tid + 256 * i;
            int mat = c >> 9, w = c & 511, row = w >> 2, cq = w & 3;
            gsrc[i] = bases[mat] + (size_t)row * H_DIM + cq * 8;
            sdst[i] = mat * MAT_BYTES + swz((uint32_t)(row * 64 + cq * 16));
        }
    }

#pragma unroll
    for (int s = 0; s < STAGES - 1; s++) {
        uint32_t sb = sbase + s * STAGE_BYTES;
#pragma unroll
        for (int i = 0; i < 6; i++) CP_ASYNC16(sb + sdst[i], gsrc[i] + s * BK);
        CP_COMMIT();
    }

    float acc[4][4][4];
#pragma unroll
    for (int a = 0; a < 4; a++)
#pragma unroll
        for (int b = 0; b < 4; b++)
#pragma unroll
            for (int c = 0; c < 4; c++) acc[a][b][c] = 0.0f;

    const uint32_t a_row = warp_m * 64 + (lid & 15);
    const uint32_t a_kb  = ((lid >> 4) & 1) * 16;
    const uint32_t b_row = warp_n * 32 + ((lid >> 4) & 1) * 8 + (lid & 7);
    const uint32_t b_kb  = ((lid >> 3) & 1) * 16;

#pragma unroll 1
    for (int kt = 0; kt < KT_N; kt++) {
        CP_WAIT2();
        __syncthreads();
        const int nt = kt + STAGES - 1;
        if (nt < KT_N) {
            uint32_t sb = sbase + (nt & 3) * STAGE_BYTES;
#pragma unroll
            for (int i = 0; i < 6; i++) CP_ASYNC16(sb + sdst[i], gsrc[i] + nt * BK);
        }
        CP_COMMIT();

        const uint32_t st = sbase + (kt & 3) * STAGE_BYTES;
#pragma unroll
        for (int kk = 0; kk < 2; kk++) {
            const uint32_t koff = kk * 32;
            uint32_t bh[2][4];
#pragma unroll
            for (int nj2 = 0; nj2 < 2; nj2++) {
                uint32_t o = swz((b_row + nj2 * 16) * 64 + koff + b_kb);
                LDSM4(bh[nj2][0], bh[nj2][1], bh[nj2][2], bh[nj2][3],
                      st + 2 * MAT_BYTES + o);
            }
#pragma unroll
            for (int mi = 0; mi < 4; mi++) {
                uint32_t ah[4], al[4];
                uint32_t o = swz((a_row + mi * 16) * 64 + koff + a_kb);
                LDSM4(ah[0], ah[1], ah[2], ah[3], st + o);
                LDSM4(al[0], al[1], al[2], al[3], st + MAT_BYTES + o);
#pragma unroll
                for (int nj = 0; nj < 4; nj++) {
                    const uint32_t b0 = bh[nj >> 1][2 * (nj & 1)];
                    const uint32_t b1 = bh[nj >> 1][2 * (nj & 1) + 1];
                    mma16816h(acc[mi][nj], ah, b0, b1);   // hi*hi
                    mma16816h(acc[mi][nj], al, b0, b1);   // lo*hi
                }
            }
        }
    }

    // ---------------- epilogue: bias + LoRA expand ----------------
    const int l4 = lid >> 2, lq = lid & 3;
    const int colbase = n0 + warp_n * 32 + 2 * lq;
    float2 bia[4];
#pragma unroll
    for (int ni = 0; ni < 4; ni++) {
        bia[ni].x = __ldg(bias + colbase + ni * 8);
        bia[ni].y = __ldg(bias + colbase + ni * 8 + 1);
    }
#pragma unroll
    for (int mi = 0; mi < 4; mi++) {
#pragma unroll
        for (int h = 0; h < 2; h++) {
            const int row = m0 + warp_m * 64 + mi * 16 + h * 8 + l4;
            const int li = g_idx32[row];
            float s[R_DIM];
            if (li >= 0) {
                const float4* s4 = (const float4*)(g_shrunk + row * R_DIM);
#pragma unroll
                for (int q = 0; q < 4; q++) {
                    float4 v = s4[q];
                    s[q * 4 + 0] = v.x; s[q * 4 + 1] = v.y;
                    s[q * 4 + 2] = v.z; s[q * 4 + 3] = v.w;
                }
            }
            float* orow = out + (size_t)row * O_DIM;
#pragma unroll
            for (int ni = 0; ni < 4; ni++) {
                const int col = colbase + ni * 8;
                float v0 = acc[mi][ni][h * 2 + 0] + bia[ni].x;
                float v1 = acc[mi][ni][h * 2 + 1] + bia[ni].y;
                if (li >= 0) {
                    const float4* b4 =
                        (const float4*)(lora_b + ((size_t)li * O_DIM + col) * R_DIM);
                    float d0 = 0.0f, d1 = 0.0f;
#pragma unroll
                    for (int q = 0; q < 4; q++) {
                        float4 bb0 = b4[q];
                        float4 bb1 = b4[q + 4];
                        d0 += s[q * 4 + 0] * bb0.x + s[q * 4 + 1] * bb0.y +
                              s[q * 4 + 2] * bb0.z + s[q * 4 + 3] * bb0.w;
                        d1 += s[q * 4 + 0] * bb1.x + s[q * 4 + 1] * bb1.y +
                              s[q * 4 + 2] * bb1.z + s[q * 4 + 3] * bb1.w;
                    }
                    v0 += d0;
                    v1 += d1;
                }
                *(float2*)(orow + col) = make_float2(v0, v1);
            }
        }
    }
}

// ---------------------------------------------------------------------------
// Stream/event resources: created once at static-init time (no device memory
// allocation; per-call work in kernel_launch is identical and deterministic).
// ---------------------------------------------------------------------------
namespace {
struct ForkJoin {
    cudaStream_t s1 = nullptr, s2 = nullptr;
    cudaEvent_t e0 = nullptr, e1 = nullptr, e2 = nullptr;
    bool ok = false;
    ForkJoin() {
        ok = (cudaStreamCreateWithFlags(&s1, cudaStreamNonBlocking) == cudaSuccess) &&
             (cudaStreamCreateWithFlags(&s2, cudaStreamNonBlocking) == cudaSuccess) &&
             (cudaEventCreateWithFlags(&e0, cudaEventDisableTiming) == cudaSuccess) &&
             (cudaEventCreateWithFlags(&e1, cudaEventDisableTiming) == cudaSuccess) &&
             (cudaEventCreateWithFlags(&e2, cudaEventDisableTiming) == cudaSuccess);
    }
};
ForkJoin g_fj;
}

// ---------------------------------------------------------------------------
extern "C" void kernel_launch(void* const* d_in, const int* in_sizes, int n_in,
                              void* d_out, int out_size) {
    const float* x      = (const float*)d_in[0];  // (T, H)
    const float* weight = (const float*)d_in[1];  // (O, H)
    const float* bias   = (const float*)d_in[2];  // (O,)
    const float* lora_a = (const float*)d_in[3];  // (L, R, H)
    const float* lora_b = (const float*)d_in[4];  // (L, O, R)
    const int*   rawidx = (const int*)d_in[5];    // (T,) int32 or int64
    float* out = (float*)d_out;                   // (T, O)

    cudaFuncSetAttribute(gemm_hmma, cudaFuncAttributeMaxDynamicSharedMemorySize,
                         DYN_SMEM);

    const int cx_blocks = (T_DIM * H_DIM / 4 + 255) / 256;
    const int cw_blocks = (O_DIM * H_DIM / 4 + 255) / 256;
    const dim3 sh_grid(L_DIM, SH_CH, SH_Z);
    const dim3 gm_grid(O_DIM / BN, T_DIM / BM);   // (32, 16)

    bucket_kernel<<<1, 256>>>(rawidx);

    if (g_fj.ok) {
        // fork: convert_w on s1, shrink3 on s2, convert_x stays on stream 0
        cudaEventRecord(g_fj.e0, 0);
        cudaStreamWaitEvent(g_fj.s1, g_fj.e0, 0);
        cudaStreamWaitEvent(g_fj.s2, g_fj.e0, 0);
        convert_w<<<cw_blocks, 256, 0, g_fj.s1>>>(weight);
        cudaEventRecord(g_fj.e1, g_fj.s1);
        shrink3<<<sh_grid, 256, 0, g_fj.s2>>>(x, lora_a);
        cudaEventRecord(g_fj.e2, g_fj.s2);
        convert_x<<<cx_blocks, 256>>>(x);
        // join
        cudaStreamWaitEvent((cudaStream_t)0, g_fj.e1, 0);
        cudaStreamWaitEvent((cudaStream_t)0, g_fj.e2, 0);
    } else {
        convert_w<<<cw_blocks, 256>>>(weight);
        shrink3<<<sh_grid, 256>>>(x, lora_a);
        convert_x<<<cx_blocks, 256>>>(x);
    }

    gemm_hmma<<<gm_grid, 256, DYN_SMEM>>>(bias, lora_b, out);
}

// round 7
// speedup vs baseline: 4.8787x; 1.3932x over previous
#include <cuda_runtime.h>
#include <cuda_fp16.h>
#include <cstdint>

#define T_DIM 2048
#define H_DIM 4096
#define O_DIM 4096
#define L_DIM 32
#define R_DIM 16

#define BM 128
#define BN 128
#define BK 32
#define KT_N (H_DIM / BK)          // 128 k-tiles
#define STAGES 4
#define MAT_BYTES 8192             // 128 rows x 64 bytes (32 fp16)
#define STAGE_BYTES (2 * MAT_BYTES)       // A + B only (single product)
#define DYN_SMEM (STAGES * STAGE_BYTES)   // 64 KB

#define SH_CH 8                    // shrink H-chunks
#define SH_Z 4                     // shrink token-split
#define CHUNK4 (H_DIM / 4 / SH_CH) // 128 float4 per chunk

// ---------------- device scratch ----------------
__device__ int    g_idx32[T_DIM];
__device__ int    g_tok[T_DIM];
__device__ int    g_cnt[L_DIM];
__device__ int    g_base[L_DIM];
__device__ float  g_shrunk[T_DIM * R_DIM];
__device__ __half g_Xhi[T_DIM * H_DIM];
__device__ __half g_Whi[O_DIM * H_DIM];

// ---------------- helpers ----------------
__device__ __forceinline__ uint32_t smem_u32(const void* p) {
    uint32_t a;
    asm("{ .reg .u64 t; cvta.to.shared.u64 t, %1; cvt.u32.u64 %0, t; }"
        : "=r"(a) : "l"(p));
    return a;
}

__device__ __forceinline__ uint32_t swz(uint32_t o) {
    return o ^ ((o >> 3) & 0x30);   // 64B-row swizzle
}

#define CP_ASYNC16(dst, src) \
    asm volatile("cp.async.cg.shared.global [%0], [%1], 16;" :: "r"(dst), "l"(src))
#define CP_COMMIT() asm volatile("cp.async.commit_group;" ::: "memory")
#define CP_WAIT2()  asm volatile("cp.async.wait_group 2;" ::: "memory")

#define LDSM4(d0, d1, d2, d3, a)                                          \
    asm volatile("ldmatrix.sync.aligned.m8n8.x4.shared.b16 {%0,%1,%2,%3}, [%4];" \
                 : "=r"(d0), "=r"(d1), "=r"(d2), "=r"(d3) : "r"(a))

__device__ __forceinline__ void mma16816h(float* c, const uint32_t* a,
                                          uint32_t b0, uint32_t b1) {
    asm volatile(
        "mma.sync.aligned.m16n8k16.row.col.f32.f16.f16.f32 "
        "{%0,%1,%2,%3}, {%4,%5,%6,%7}, {%8,%9}, {%0,%1,%2,%3};"
        : "+f"(c[0]), "+f"(c[1]), "+f"(c[2]), "+f"(c[3])
        : "r"(a[0]), "r"(a[1]), "r"(a[2]), "r"(a[3]), "r"(b0), "r"(b1));
}

// ---------------------------------------------------------------------------
// Kernel 1: index decode (int64 vs int32) + bucket tokens + zero g_shrunk.
// ---------------------------------------------------------------------------
__global__ void bucket_kernel(const int* __restrict__ raw) {
    __shared__ int bad;
    __shared__ int s_cnt[L_DIM];
    __shared__ int s_base[L_DIM];
    const int tid = threadIdx.x;
    if (tid == 0) bad = 0;
    if (tid < L_DIM) s_cnt[tid] = 0;
    __syncthreads();
    {   // 256 pairs = 2048 bytes, in-bounds for either width
        int lo = raw[2 * tid], hi = raw[2 * tid + 1];
        bool ok = (hi == 0 && lo >= 0) || (hi == -1 && lo < 0);
        if (!ok) bad = 1;
    }
    __syncthreads();
    const bool is64 = (bad == 0);
    for (int t = tid; t < T_DIM; t += 256) {
        int v = is64 ? raw[2 * t] : raw[t];
        g_idx32[t] = v;
        if (v >= 0) atomicAdd(&s_cnt[v], 1);
    }
    for (int i = tid; i < T_DIM * R_DIM / 4; i += 256)
        ((float4*)g_shrunk)[i] = make_float4(0, 0, 0, 0);
    __syncthreads();
    if (tid == 0) {
        int a = 0;
        for (int l = 0; l < L_DIM; l++) { s_base[l] = a; a += s_cnt[l]; }
    }
    __syncthreads();
    if (tid < L_DIM) {
        g_cnt[tid] = s_cnt[tid];
        g_base[tid] = s_base[tid];
        s_cnt[tid] = 0;
    }
    __syncthreads();
    for (int t = tid; t < T_DIM; t += 256) {
        int v = g_idx32[t];
        if (v >= 0) {
            int p = atomicAdd(&s_cnt[v], 1);
            g_tok[s_base[v] + p] = t;
        }
    }
}

// ---------------------------------------------------------------------------
// Kernel 2a: fp32 -> fp16 of X
// ---------------------------------------------------------------------------
__global__ void convert_x(const float* __restrict__ src) {
    int i = blockIdx.x * blockDim.x + threadIdx.x;
    if (i >= T_DIM * H_DIM / 4) return;
    float4 v = ((const float4*)src)[i];
    uint2 ph;
    ph.x = ((uint32_t)__half_as_ushort(__float2half(v.y)) << 16) |
           __half_as_ushort(__float2half(v.x));
    ph.y = ((uint32_t)__half_as_ushort(__float2half(v.w)) << 16) |
           __half_as_ushort(__float2half(v.z));
    ((uint2*)g_Xhi)[i] = ph;
}

// ---------------------------------------------------------------------------
// Kernel 2b: fp32 -> fp16 of W
// ---------------------------------------------------------------------------
__global__ void convert_w(const float* __restrict__ src) {
    int i = blockIdx.x * blockDim.x + threadIdx.x;
    if (i >= O_DIM * H_DIM / 4) return;
    float4 v = ((const float4*)src)[i];
    uint2 ph;
    ph.x = ((uint32_t)__half_as_ushort(__float2half(v.y)) << 16) |
           __half_as_ushort(__float2half(v.x));
    ph.y = ((uint32_t)__half_as_ushort(__float2half(v.w)) << 16) |
           __half_as_ushort(__float2half(v.z));
    ((uint2*)g_Whi)[i] = ph;
}

// ---------------------------------------------------------------------------
// Kernel 3: LoRA shrink, grid (32 adapters, 8 H-chunks, 4 token-slices),
//   256 thr, A-chunk in SMEM, warp-slot strides 32 tokens.
// ---------------------------------------------------------------------------
__global__ __launch_bounds__(256) void shrink3(
    const float* __restrict__ x, const float* __restrict__ lora_a) {
    __shared__ float4 sA4[R_DIM * CHUNK4];       // 16 x 128 float4 = 32 KB
    const int l = blockIdx.x;
    const int n = g_cnt[l];
    if (n == 0) return;
    const int tid = threadIdx.x;
    const int wid = tid >> 5, lid = tid & 31;
    const int slot = blockIdx.z * 8 + wid;       // 0..31
    if (blockIdx.z * 8 >= n) return;             // whole block idle -> skip
    const int hb4 = blockIdx.y * CHUNK4;

    const float4* a4 = ((const float4*)lora_a) + (size_t)l * R_DIM * (H_DIM / 4);
    for (int i = tid; i < R_DIM * CHUNK4; i += 256) {
        int r = i / CHUNK4, j4 = i % CHUNK4;
        sA4[i] = a4[r * (H_DIM / 4) + hb4 + j4];
    }
    __syncthreads();

    const int base = g_base[l];
    for (int ti = slot; ti < n; ti += 32) {
        const int t = g_tok[base + ti];
        const float4* x4 = ((const float4*)x) + (size_t)t * (H_DIM / 4) + hb4;
        float4 xv[4];
#pragma unroll
        for (int j = 0; j < 4; j++) xv[j] = x4[lid + 32 * j];
        float acc[R_DIM];
#pragma unroll
        for (int r = 0; r < R_DIM; r++) acc[r] = 0.0f;
#pragma unroll
        for (int j = 0; j < 4; j++) {
#pragma unroll
            for (int r = 0; r < R_DIM; r++) {
                float4 av = sA4[r * CHUNK4 + lid + 32 * j];
                acc[r] += xv[j].x * av.x + xv[j].y * av.y +
                          xv[j].z * av.z + xv[j].w * av.w;
            }
        }
#pragma unroll
        for (int r = 0; r < R_DIM; r++) {
            float v = acc[r];
#pragma unroll
            for (int off = 16; off > 0; off >>= 1)
                v += __shfl_down_sync(0xffffffff, v, off);
            if (lid == 0) atomicAdd(&g_shrunk[t * R_DIM + r], v);
        }
    }
}

// ---------------------------------------------------------------------------
// Kernel 4: fp16 HMMA GEMM, single product Xhi*Whi + fused LoRA epilogue
//   128x128x32 tiles, 4-stage cp.async, 8 warps, occupancy 2.
// ---------------------------------------------------------------------------
__global__ void __launch_bounds__(256, 2) gemm_hmma(
    const float* __restrict__ bias, const float* __restrict__ lora_b,
    float* __restrict__ out) {
    extern __shared__ char dynsmem[];
    const uint32_t sbase = smem_u32(dynsmem);
    const int tid = threadIdx.x;
    const int wid = tid >> 5, lid = tid & 31;
    const int m0 = blockIdx.y * BM, n0 = blockIdx.x * BN;
    const int warp_m = wid & 1;
    const int warp_n = wid >> 1;

    // loader precompute: 4 x 16B per thread per stage (2 matrices x 512 chunks)
    const __half* gsrc[4];
    uint32_t sdst[4];
    {
        const __half* bases[2] = {
            g_Xhi + (size_t)m0 * H_DIM, g_Whi + (size_t)n0 * H_DIM};
#pragma unroll
        for (int i = 0; i < 4; i++) {
            int c = tid + 256 * i;
            int mat = c >> 9, w = c & 511, row = w >> 2, cq = w & 3;
            gsrc[i] = bases[mat] + (size_t)row * H_DIM + cq * 8;
            sdst[i] = mat * MAT_BYTES + swz((uint32_t)(row * 64 + cq * 16));
        }
    }

#pragma unroll
    for (int s = 0; s < STAGES - 1; s++) {
        uint32_t sb = sbase + s * STAGE_BYTES;
#pragma unroll
        for (int i = 0; i < 4; i++) CP_ASYNC16(sb + sdst[i], gsrc[i] + s * BK);
        CP_COMMIT();
    }

    float acc[4][4][4];
#pragma unroll
    for (int a = 0; a < 4; a++)
#pragma unroll
        for (int b = 0; b < 4; b++)
#pragma unroll
            for (int c = 0; c < 4; c++) acc[a][b][c] = 0.0f;

    const uint32_t a_row = warp_m * 64 + (lid & 15);
    const uint32_t a_kb  = ((lid >> 4) & 1) * 16;
    const uint32_t b_row = warp_n * 32 + ((lid >> 4) & 1) * 8 + (lid & 7);
    const uint32_t b_kb  = ((lid >> 3) & 1) * 16;

#pragma unroll 1
    for (int kt = 0; kt < KT_N; kt++) {
        CP_WAIT2();
        __syncthreads();
        const int nt = kt + STAGES - 1;
        if (nt < KT_N) {
            uint32_t sb = sbase + (nt & 3) * STAGE_BYTES;
#pragma unroll
            for (int i = 0; i < 4; i++) CP_ASYNC16(sb + sdst[i], gsrc[i] + nt * BK);
        }
        CP_COMMIT();

        const uint32_t st = sbase + (kt & 3) * STAGE_BYTES;
#pragma unroll
        for (int kk = 0; kk < 2; kk++) {
            const uint32_t koff = kk * 32;
            uint32_t bh[2][4];
#pragma unroll
            for (int nj2 = 0; nj2 < 2; nj2++) {
                uint32_t o = swz((b_row + nj2 * 16) * 64 + koff + b_kb);
                LDSM4(bh[nj2][0], bh[nj2][1], bh[nj2][2], bh[nj2][3],
                      st + MAT_BYTES + o);
            }
#pragma unroll
            for (int mi = 0; mi < 4; mi++) {
                uint32_t ah[4];
                uint32_t o = swz((a_row + mi * 16) * 64 + koff + a_kb);
                LDSM4(ah[0], ah[1], ah[2], ah[3], st + o);
#pragma unroll
                for (int nj = 0; nj < 4; nj++) {
                    const uint32_t b0 = bh[nj >> 1][2 * (nj & 1)];
                    const uint32_t b1 = bh[nj >> 1][2 * (nj & 1) + 1];
                    mma16816h(acc[mi][nj], ah, b0, b1);
                }
            }
        }
    }

    // ---------------- epilogue: bias + LoRA expand ----------------
    const int l4 = lid >> 2, lq = lid & 3;
    const int colbase = n0 + warp_n * 32 + 2 * lq;
    float2 bia[4];
#pragma unroll
    for (int ni = 0; ni < 4; ni++) {
        bia[ni].x = __ldg(bias + colbase + ni * 8);
        bia[ni].y = __ldg(bias + colbase + ni * 8 + 1);
    }
#pragma unroll
    for (int mi = 0; mi < 4; mi++) {
#pragma unroll
        for (int h = 0; h < 2; h++) {
            const int row = m0 + warp_m * 64 + mi * 16 + h * 8 + l4;
            const int li = g_idx32[row];
            float s[R_DIM];
            if (li >= 0) {
                const float4* s4 = (const float4*)(g_shrunk + row * R_DIM);
#pragma unroll
                for (int q = 0; q < 4; q++) {
                    float4 v = s4[q];
                    s[q * 4 + 0] = v.x; s[q * 4 + 1] = v.y;
                    s[q * 4 + 2] = v.z; s[q * 4 + 3] = v.w;
                }
            }
            float* orow = out + (size_t)row * O_DIM;
#pragma unroll
            for (int ni = 0; ni < 4; ni++) {
                const int col = colbase + ni * 8;
                float v0 = acc[mi][ni][h * 2 + 0] + bia[ni].x;
                float v1 = acc[mi][ni][h * 2 + 1] + bia[ni].y;
                if (li >= 0) {
                    const float4* b4 =
                        (const float4*)(lora_b + ((size_t)li * O_DIM + col) * R_DIM);
                    float d0 = 0.0f, d1 = 0.0f;
#pragma unroll
                    for (int q = 0; q < 4; q++) {
                        float4 bb0 = b4[q];
                        float4 bb1 = b4[q + 4];
                        d0 += s[q * 4 + 0] * bb0.x + s[q * 4 + 1] * bb0.y +
                              s[q * 4 + 2] * bb0.z + s[q * 4 + 3] * bb0.w;
                        d1 += s[q * 4 + 0] * bb1.x + s[q * 4 + 1] * bb1.y +
                              s[q * 4 + 2] * bb1.z + s[q * 4 + 3] * bb1.w;
                    }
                    v0 += d0;
                    v1 += d1;
                }
                *(float2*)(orow + col) = make_float2(v0, v1);
            }
        }
    }
}

// ---------------------------------------------------------------------------
// Stream/event resources: created once at static-init time.
// ---------------------------------------------------------------------------
namespace {
struct ForkJoin {
    cudaStream_t s1 = nullptr, s2 = nullptr;
    cudaEvent_t e0 = nullptr, e1 = nullptr, e2 = nullptr;
    bool ok = false;
    ForkJoin() {
        ok = (cudaStreamCreateWithFlags(&s1, cudaStreamNonBlocking) == cudaSuccess) &&
             (cudaStreamCreateWithFlags(&s2, cudaStreamNonBlocking) == cudaSuccess) &&
             (cudaEventCreateWithFlags(&e0, cudaEventDisableTiming) == cudaSuccess) &&
             (cudaEventCreateWithFlags(&e1, cudaEventDisableTiming) == cudaSuccess) &&
             (cudaEventCreateWithFlags(&e2, cudaEventDisableTiming) == cudaSuccess);
    }
};
ForkJoin g_fj;
}

// ---------------------------------------------------------------------------
extern "C" void kernel_launch(void* const* d_in, const int* in_sizes, int n_in,
                              void* d_out, int out_size) {
    const float* x      = (const float*)d_in[0];  // (T, H)
    const float* weight = (const float*)d_in[1];  // (O, H)
    const float* bias   = (const float*)d_in[2];  // (O,)
    const float* lora_a = (const float*)d_in[3];  // (L, R, H)
    const float* lora_b = (const float*)d_in[4];  // (L, O, R)
    const int*   rawidx = (const int*)d_in[5];    // (T,) int32 or int64
    float* out = (float*)d_out;                   // (T, O)

    cudaFuncSetAttribute(gemm_hmma, cudaFuncAttributeMaxDynamicSharedMemorySize,
                         DYN_SMEM);

    const int cx_blocks = (T_DIM * H_DIM / 4 + 255) / 256;
    const int cw_blocks = (O_DIM * H_DIM / 4 + 255) / 256;
    const dim3 sh_grid(L_DIM, SH_CH, SH_Z);
    const dim3 gm_grid(O_DIM / BN, T_DIM / BM);   // (32, 16)

    bucket_kernel<<<1, 256>>>(rawidx);

    if (g_fj.ok) {
        // fork: convert_w on s1, shrink3 on s2, convert_x stays on stream 0
        cudaEventRecord(g_fj.e0, 0);
        cudaStreamWaitEvent(g_fj.s1, g_fj.e0, 0);
        cudaStreamWaitEvent(g_fj.s2, g_fj.e0, 0);
        convert_w<<<cw_blocks, 256, 0, g_fj.s1>>>(weight);
        cudaEventRecord(g_fj.e1, g_fj.s1);
        shrink3<<<sh_grid, 256, 0, g_fj.s2>>>(x, lora_a);
        cudaEventRecord(g_fj.e2, g_fj.s2);
        convert_x<<<cx_blocks, 256>>>(x);
        // join
        cudaStreamWaitEvent((cudaStream_t)0, g_fj.e1, 0);
        cudaStreamWaitEvent((cudaStream_t)0, g_fj.e2, 0);
    } else {
        convert_w<<<cw_blocks, 256>>>(weight);
        shrink3<<<sh_grid, 256>>>(x, lora_a);
        convert_x<<<cx_blocks, 256>>>(x);
    }

    gemm_hmma<<<gm_grid, 256, DYN_SMEM>>>(bias, lora_b, out);
}

// round 8
// speedup vs baseline: 5.8385x; 1.1967x over previous
#include <cuda_runtime.h>
#include <cuda_fp16.h>
#include <cstdint>

#define T_DIM 2048
#define H_DIM 4096
#define O_DIM 4096
#define L_DIM 32
#define R_DIM 16

#define BM 128
#define BN 128
#define BK 32
#define KT_N (H_DIM / BK)          // 128 k-tiles
#define STAGES 4
#define MAT_BYTES 8192             // 128 rows x 64 bytes (32 fp16)
#define STAGE_BYTES (2 * MAT_BYTES)       // A + B (single product)
#define DYN_SMEM (STAGES * STAGE_BYTES)   // 64 KB

#define SH_CH 8                    // shrink H-chunks
#define SH_Z 4                     // shrink token-split
#define CHUNK4 (H_DIM / 4 / SH_CH) // 128 float4 per chunk

// ---------------- device scratch ----------------
__device__ int    g_idx32[T_DIM];
__device__ int    g_tok[T_DIM];
__device__ int    g_cnt[L_DIM];
__device__ int    g_base[L_DIM];
__device__ float  g_shrunk[T_DIM * R_DIM];
__device__ __half g_lora[(size_t)T_DIM * O_DIM];   // fp16 LoRA contribution
__device__ __half g_Xhi[T_DIM * H_DIM];
__device__ __half g_Whi[O_DIM * H_DIM];

// ---------------- helpers ----------------
__device__ __forceinline__ uint32_t smem_u32(const void* p) {
    uint32_t a;
    asm("{ .reg .u64 t; cvta.to.shared.u64 t, %1; cvt.u32.u64 %0, t; }"
        : "=r"(a) : "l"(p));
    return a;
}

__device__ __forceinline__ uint32_t swz(uint32_t o) {
    return o ^ ((o >> 3) & 0x30);   // 64B-row swizzle
}

#define CP_ASYNC16(dst, src) \
    asm volatile("cp.async.cg.shared.global [%0], [%1], 16;" :: "r"(dst), "l"(src))
#define CP_COMMIT() asm volatile("cp.async.commit_group;" ::: "memory")
#define CP_WAIT2()  asm volatile("cp.async.wait_group 2;" ::: "memory")

#define LDSM4(d0, d1, d2, d3, a)                                          \
    asm volatile("ldmatrix.sync.aligned.m8n8.x4.shared.b16 {%0,%1,%2,%3}, [%4];" \
                 : "=r"(d0), "=r"(d1), "=r"(d2), "=r"(d3) : "r"(a))

__device__ __forceinline__ void mma16816h(float* c, const uint32_t* a,
                                          uint32_t b0, uint32_t b1) {
    asm volatile(
        "mma.sync.aligned.m16n8k16.row.col.f32.f16.f16.f32 "
        "{%0,%1,%2,%3}, {%4,%5,%6,%7}, {%8,%9}, {%0,%1,%2,%3};"
        : "+f"(c[0]), "+f"(c[1]), "+f"(c[2]), "+f"(c[3])
        : "r"(a[0]), "r"(a[1]), "r"(a[2]), "r"(a[3]), "r"(b0), "r"(b1));
}

// ---------------------------------------------------------------------------
// Kernel 1: index decode (int64 vs int32) + bucket tokens + zero g_shrunk.
// ---------------------------------------------------------------------------
__global__ void bucket_kernel(const int* __restrict__ raw) {
    __shared__ int bad;
    __shared__ int s_cnt[L_DIM];
    __shared__ int s_base[L_DIM];
    const int tid = threadIdx.x;
    if (tid == 0) bad = 0;
    if (tid < L_DIM) s_cnt[tid] = 0;
    __syncthreads();
    {   // 256 pairs = 2048 bytes, in-bounds for either width
        int lo = raw[2 * tid], hi = raw[2 * tid + 1];
        bool ok = (hi == 0 && lo >= 0) || (hi == -1 && lo < 0);
        if (!ok) bad = 1;
    }
    __syncthreads();
    const bool is64 = (bad == 0);
    for (int t = tid; t < T_DIM; t += 256) {
        int v = is64 ? raw[2 * t] : raw[t];
        g_idx32[t] = v;
        if (v >= 0) atomicAdd(&s_cnt[v], 1);
    }
    for (int i = tid; i < T_DIM * R_DIM / 4; i += 256)
        ((float4*)g_shrunk)[i] = make_float4(0, 0, 0, 0);
    __syncthreads();
    if (tid == 0) {
        int a = 0;
        for (int l = 0; l < L_DIM; l++) { s_base[l] = a; a += s_cnt[l]; }
    }
    __syncthreads();
    if (tid < L_DIM) {
        g_cnt[tid] = s_cnt[tid];
        g_base[tid] = s_base[tid];
        s_cnt[tid] = 0;
    }
    __syncthreads();
    for (int t = tid; t < T_DIM; t += 256) {
        int v = g_idx32[t];
        if (v >= 0) {
            int p = atomicAdd(&s_cnt[v], 1);
            g_tok[s_base[v] + p] = t;
        }
    }
}

// ---------------------------------------------------------------------------
// Kernel 2a: fp32 -> fp16 of X
// ---------------------------------------------------------------------------
__global__ void convert_x(const float* __restrict__ src) {
    int i = blockIdx.x * blockDim.x + threadIdx.x;
    if (i >= T_DIM * H_DIM / 4) return;
    float4 v = ((const float4*)src)[i];
    uint2 ph;
    ph.x = ((uint32_t)__half_as_ushort(__float2half(v.y)) << 16) |
           __half_as_ushort(__float2half(v.x));
    ph.y = ((uint32_t)__half_as_ushort(__float2half(v.w)) << 16) |
           __half_as_ushort(__float2half(v.z));
    ((uint2*)g_Xhi)[i] = ph;
}

// ---------------------------------------------------------------------------
// Kernel 2b: fp32 -> fp16 of W
// ---------------------------------------------------------------------------
__global__ void convert_w(const float* __restrict__ src) {
    int i = blockIdx.x * blockDim.x + threadIdx.x;
    if (i >= O_DIM * H_DIM / 4) return;
    float4 v = ((const float4*)src)[i];
    uint2 ph;
    ph.x = ((uint32_t)__half_as_ushort(__float2half(v.y)) << 16) |
           __half_as_ushort(__float2half(v.x));
    ph.y = ((uint32_t)__half_as_ushort(__float2half(v.w)) << 16) |
           __half_as_ushort(__float2half(v.z));
    ((uint2*)g_Whi)[i] = ph;
}

// ---------------------------------------------------------------------------
// Kernel 3: LoRA shrink, grid (32 adapters, 8 H-chunks, 4 token-slices).
// ---------------------------------------------------------------------------
__global__ __launch_bounds__(256) void shrink3(
    const float* __restrict__ x, const float* __restrict__ lora_a) {
    __shared__ float4 sA4[R_DIM * CHUNK4];       // 16 x 128 float4 = 32 KB
    const int l = blockIdx.x;
    const int n = g_cnt[l];
    if (n == 0) return;
    const int tid = threadIdx.x;
    const int wid = tid >> 5, lid = tid & 31;
    const int slot = blockIdx.z * 8 + wid;       // 0..31
    if (blockIdx.z * 8 >= n) return;             // whole block idle -> skip
    const int hb4 = blockIdx.y * CHUNK4;

    const float4* a4 = ((const float4*)lora_a) + (size_t)l * R_DIM * (H_DIM / 4);
    for (int i = tid; i < R_DIM * CHUNK4; i += 256) {
        int r = i / CHUNK4, j4 = i % CHUNK4;
        sA4[i] = a4[r * (H_DIM / 4) + hb4 + j4];
    }
    __syncthreads();

    const int base = g_base[l];
    for (int ti = slot; ti < n; ti += 32) {
        const int t = g_tok[base + ti];
        const float4* x4 = ((const float4*)x) + (size_t)t * (H_DIM / 4) + hb4;
        float4 xv[4];
#pragma unroll
        for (int j = 0; j < 4; j++) xv[j] = x4[lid + 32 * j];
        float acc[R_DIM];
#pragma unroll
        for (int r = 0; r < R_DIM; r++) acc[r] = 0.0f;
#pragma unroll
        for (int j = 0; j < 4; j++) {
#pragma unroll
            for (int r = 0; r < R_DIM; r++) {
                float4 av = sA4[r * CHUNK4 + lid + 32 * j];
                acc[r] += xv[j].x * av.x + xv[j].y * av.y +
                          xv[j].z * av.z + xv[j].w * av.w;
            }
        }
#pragma unroll
        for (int r = 0; r < R_DIM; r++) {
            float v = acc[r];
#pragma unroll
            for (int off = 16; off > 0; off >>= 1)
                v += __shfl_down_sync(0xffffffff, v, off);
            if (lid == 0) atomicAdd(&g_shrunk[t * R_DIM + r], v);
        }
    }
}

// ---------------------------------------------------------------------------
// Kernel 3b: LoRA expand by adapter: g_lora[t, c] = shrunk[t,:] . B[l, c, :]
//   grid (32 adapters, 8 col-chunks of 512). Thread owns 2 cols of B in regs.
//   Only active tokens are written; inactive rows are never read downstream.
// ---------------------------------------------------------------------------
__global__ __launch_bounds__(256) void expand_kernel(
    const float* __restrict__ lora_b) {
    const int l = blockIdx.x;
    const int n = g_cnt[l];
    if (n == 0) return;
    const int c0 = blockIdx.y * 512 + threadIdx.x * 2;

    const float4* b0 = (const float4*)(lora_b + ((size_t)l * O_DIM + c0) * R_DIM);
    const float4* b1 = (const float4*)(lora_b + ((size_t)l * O_DIM + c0 + 1) * R_DIM);
    float4 B0[4], B1[4];
#pragma unroll
    for (int q = 0; q < 4; q++) { B0[q] = b0[q]; B1[q] = b1[q]; }

    const int base = g_base[l];
    for (int ti = 0; ti < n; ti++) {
        const int t = g_tok[base + ti];
        const float4* s4 = (const float4*)(g_shrunk + t * R_DIM);
        float d0 = 0.0f, d1 = 0.0f;
#pragma unroll
        for (int q = 0; q < 4; q++) {
            float4 s = s4[q];
            d0 += s.x * B0[q].x + s.y * B0[q].y + s.z * B0[q].z + s.w * B0[q].w;
            d1 += s.x * B1[q].x + s.y * B1[q].y + s.z * B1[q].z + s.w * B1[q].w;
        }
        *(__half2*)(g_lora + (size_t)t * O_DIM + c0) = __floats2half2_rn(d0, d1);
    }
}

// ---------------------------------------------------------------------------
// Kernel 4: fp16 HMMA GEMM, single product + lightweight epilogue
//   (bias + precomputed fp16 LoRA term). 128x128x32, 4-stage cp.async, occ 2.
// ---------------------------------------------------------------------------
__global__ void __launch_bounds__(256, 2) gemm_hmma(
    const float* __restrict__ bias, float* __restrict__ out) {
    extern __shared__ char dynsmem[];
    const uint32_t sbase = smem_u32(dynsmem);
    const int tid = threadIdx.x;
    const int wid = tid >> 5, lid = tid & 31;
    const int m0 = blockIdx.y * BM, n0 = blockIdx.x * BN;
    const int warp_m = wid & 1;
    const int warp_n = wid >> 1;

    const __half* gsrc[4];
    uint32_t sdst[4];
    {
        const __half* bases[2] = {
            g_Xhi + (size_t)m0 * H_DIM, g_Whi + (size_t)n0 * H_DIM};
#pragma unroll
        for (int i = 0; i < 4; i++) {
            int c = tid + 256 * i;
            int mat = c >> 9, w = c & 511, row = w >> 2, cq = w & 3;
            gsrc[i] = bases[mat] + (size_t)row * H_DIM + cq * 8;
            sdst[i] = mat * MAT_BYTES + swz((uint32_t)(row * 64 + cq * 16));
        }
    }

#pragma unroll
    for (int s = 0; s < STAGES - 1; s++) {
        uint32_t sb = sbase + s * STAGE_BYTES;
#pragma unroll
        for (int i = 0; i < 4; i++) CP_ASYNC16(sb + sdst[i], gsrc[i] + s * BK);
        CP_COMMIT();
    }

    float acc[4][4][4];
#pragma unroll
    for (int a = 0; a < 4; a++)
#pragma unroll
        for (int b = 0; b < 4; b++)
#pragma unroll
            for (int c = 0; c < 4; c++) acc[a][b][c] = 0.0f;

    const uint32_t a_row = warp_m * 64 + (lid & 15);
    const uint32_t a_kb  = ((lid >> 4) & 1) * 16;
    const uint32_t b_row = warp_n * 32 + ((lid >> 4) & 1) * 8 + (lid & 7);
    const uint32_t b_kb  = ((lid >> 3) & 1) * 16;

#pragma unroll 1
    for (int kt = 0; kt < KT_N; kt++) {
        CP_WAIT2();
        __syncthreads();
        const int nt = kt + STAGES - 1;
        if (nt < KT_N) {
            uint32_t sb = sbase + (nt & 3) * STAGE_BYTES;
#pragma unroll
            for (int i = 0; i < 4; i++) CP_ASYNC16(sb + sdst[i], gsrc[i] + nt * BK);
        }
        CP_COMMIT();

        const uint32_t st = sbase + (kt & 3) * STAGE_BYTES;
#pragma unroll
        for (int kk = 0; kk < 2; kk++) {
            const uint32_t koff = kk * 32;
            uint32_t bh[2][4];
#pragma unroll
            for (int nj2 = 0; nj2 < 2; nj2++) {
                uint32_t o = swz((b_row + nj2 * 16) * 64 + koff + b_kb);
                LDSM4(bh[nj2][0], bh[nj2][1], bh[nj2][2], bh[nj2][3],
                      st + MAT_BYTES + o);
            }
#pragma unroll
            for (int mi = 0; mi < 4; mi++) {
                uint32_t ah[4];
                uint32_t o = swz((a_row + mi * 16) * 64 + koff + a_kb);
                LDSM4(ah[0], ah[1], ah[2], ah[3], st + o);
#pragma unroll
                for (int nj = 0; nj < 4; nj++) {
                    const uint32_t b0 = bh[nj >> 1][2 * (nj & 1)];
                    const uint32_t b1 = bh[nj >> 1][2 * (nj & 1) + 1];
                    mma16816h(acc[mi][nj], ah, b0, b1);
                }
            }
        }
    }

    // ---------------- epilogue: bias + precomputed fp16 LoRA term ----------
    const int l4 = lid >> 2, lq = lid & 3;
    const int colbase = n0 + warp_n * 32 + 2 * lq;   // even
    float2 bia[4];
#pragma unroll
    for (int ni = 0; ni < 4; ni++) {
        bia[ni].x = __ldg(bias + colbase + ni * 8);
        bia[ni].y = __ldg(bias + colbase + ni * 8 + 1);
    }
#pragma unroll
    for (int mi = 0; mi < 4; mi++) {
#pragma unroll
        for (int h = 0; h < 2; h++) {
            const int row = m0 + warp_m * 64 + mi * 16 + h * 8 + l4;
            const int li = g_idx32[row];
            float* orow = out + (size_t)row * O_DIM;
            const __half2* lrow =
                (const __half2*)(g_lora + (size_t)row * O_DIM + colbase);
#pragma unroll
            for (int ni = 0; ni < 4; ni++) {
                const int col = colbase + ni * 8;
                float v0 = acc[mi][ni][h * 2 + 0] + bia[ni].x;
                float v1 = acc[mi][ni][h * 2 + 1] + bia[ni].y;
                if (li >= 0) {
                    __half2 hv = lrow[ni * 4];
                    v0 += __low2float(hv);
                    v1 += __high2float(hv);
                }
                *(float2*)(orow + col) = make_float2(v0, v1);
            }
        }
    }
}

// ---------------------------------------------------------------------------
// Stream/event resources: created once at static-init time.
// ---------------------------------------------------------------------------
namespace {
struct ForkJoin {
    cudaStream_t s1 = nullptr, s2 = nullptr;
    cudaEvent_t e0 = nullptr, e1 = nullptr, e2 = nullptr;
    bool ok = false;
    ForkJoin() {
        ok = (cudaStreamCreateWithFlags(&s1, cudaStreamNonBlocking) == cudaSuccess) &&
             (cudaStreamCreateWithFlags(&s2, cudaStreamNonBlocking) == cudaSuccess) &&
             (cudaEventCreateWithFlags(&e0, cudaEventDisableTiming) == cudaSuccess) &&
             (cudaEventCreateWithFlags(&e1, cudaEventDisableTiming) == cudaSuccess) &&
             (cudaEventCreateWithFlags(&e2, cudaEventDisableTiming) == cudaSuccess);
    }
};
ForkJoin g_fj;
}

// ---------------------------------------------------------------------------
extern "C" void kernel_launch(void* const* d_in, const int* in_sizes, int n_in,
                              void* d_out, int out_size) {
    const float* x      = (const float*)d_in[0];  // (T, H)
    const float* weight = (const float*)d_in[1];  // (O, H)
    const float* bias   = (const float*)d_in[2];  // (O,)
    const float* lora_a = (const float*)d_in[3];  // (L, R, H)
    const float* lora_b = (const float*)d_in[4];  // (L, O, R)
    const int*   rawidx = (const int*)d_in[5];    // (T,) int32 or int64
    float* out = (float*)d_out;                   // (T, O)

    cudaFuncSetAttribute(gemm_hmma, cudaFuncAttributeMaxDynamicSharedMemorySize,
                         DYN_SMEM);

    const int cx_blocks = (T_DIM * H_DIM / 4 + 255) / 256;
    const int cw_blocks = (O_DIM * H_DIM / 4 + 255) / 256;
    const dim3 sh_grid(L_DIM, SH_CH, SH_Z);
    const dim3 ex_grid(L_DIM, O_DIM / 512);
    const dim3 gm_grid(O_DIM / BN, T_DIM / BM);   // (32, 16)

    if (g_fj.ok) {
        // convert_w has no dependency on bucket -> fork immediately
        cudaEventRecord(g_fj.e0, 0);
        cudaStreamWaitEvent(g_fj.s1, g_fj.e0, 0);
        convert_w<<<cw_blocks, 256, 0, g_fj.s1>>>(weight);
        cudaEventRecord(g_fj.e1, g_fj.s1);

        // stream 0: bucket, then fork shrink->expand chain onto s2
        bucket_kernel<<<1, 256>>>(rawidx);
        cudaEventRecord(g_fj.e0, 0);
        cudaStreamWaitEvent(g_fj.s2, g_fj.e0, 0);
        shrink3<<<sh_grid, 256, 0, g_fj.s2>>>(x, lora_a);
        expand_kernel<<<ex_grid, 256, 0, g_fj.s2>>>(lora_b);
        cudaEventRecord(g_fj.e2, g_fj.s2);

        convert_x<<<cx_blocks, 256>>>(x);

        // join
        cudaStreamWaitEvent((cudaStream_t)0, g_fj.e1, 0);
        cudaStreamWaitEvent((cudaStream_t)0, g_fj.e2, 0);
    } else {
        convert_w<<<cw_blocks, 256>>>(weight);
        bucket_kernel<<<1, 256>>>(rawidx);
        shrink3<<<sh_grid, 256>>>(x, lora_a);
        expand_kernel<<<ex_grid, 256>>>(lora_b);
        convert_x<<<cx_blocks, 256>>>(x);
    }

    gemm_hmma<<<gm_grid, 256, DYN_SMEM>>>(bias, out);
}

// round 10
// speedup vs baseline: 5.8770x; 1.0066x over previous
#include <cuda_runtime.h>
#include <cuda_fp16.h>
#include <cstdint>

#define T_DIM 2048
#define H_DIM 4096
#define O_DIM 4096
#define L_DIM 32
#define R_DIM 16

#define BM 128
#define BN 128
#define BK 32
#define KT_N (H_DIM / BK)          // 128 k-tiles
#define STAGES 4
#define MAT_BYTES 8192             // 128 rows x 64 bytes (32 fp16)
#define STAGE_BYTES (2 * MAT_BYTES)       // A + B (single product)
#define DYN_SMEM (STAGES * STAGE_BYTES)   // 64 KB

#define SH_CH 8                    // shrink H-chunks
#define SH_Z 8                     // shrink token-split
#define CHUNK4 (H_DIM / 4 / SH_CH) // 128 float4 per chunk
#define EX_Z 4                     // expand token-split

// ---------------- device scratch ----------------
__device__ int    g_idx32[T_DIM];
__device__ int    g_tok[T_DIM];
__device__ int    g_cnt[L_DIM];
__device__ int    g_base[L_DIM];
__device__ float  g_shrunk[T_DIM * R_DIM];
__device__ __half g_lora[(size_t)T_DIM * O_DIM];   // fp16 LoRA contribution
__device__ __half g_Xhi[T_DIM * H_DIM];
__device__ __half g_Whi[O_DIM * H_DIM];

// ---------------- helpers ----------------
__device__ __forceinline__ uint32_t smem_u32(const void* p) {
    uint32_t a;
    asm("{ .reg .u64 t; cvta.to.shared.u64 t, %1; cvt.u32.u64 %0, t; }"
        : "=r"(a) : "l"(p));
    return a;
}

__device__ __forceinline__ uint32_t swz(uint32_t o) {
    return o ^ ((o >> 3) & 0x30);   // 64B-row swizzle
}

#define CP_ASYNC16(dst, src) \
    asm volatile("cp.async.cg.shared.global [%0], [%1], 16;" :: "r"(dst), "l"(src))
#define CP_COMMIT() asm volatile("cp.async.commit_group;" ::: "memory")
#define CP_WAIT2()  asm volatile("cp.async.wait_group 2;" ::: "memory")

#define LDSM4(d0, d1, d2, d3, a)                                          \
    asm volatile("ldmatrix.sync.aligned.m8n8.x4.shared.b16 {%0,%1,%2,%3}, [%4];" \
                 : "=r"(d0), "=r"(d1), "=r"(d2), "=r"(d3) : "r"(a))

__device__ __forceinline__ void mma16816h(float* c, const uint32_t* a,
                                          uint32_t b0, uint32_t b1) {
    asm volatile(
        "mma.sync.aligned.m16n8k16.row.col.f32.f16.f16.f32 "
        "{%0,%1,%2,%3}, {%4,%5,%6,%7}, {%8,%9}, {%0,%1,%2,%3};"
        : "+f"(c[0]), "+f"(c[1]), "+f"(c[2]), "+f"(c[3])
        : "r"(a[0]), "r"(a[1]), "r"(a[2]), "r"(a[3]), "r"(b0), "r"(b1));
}

// ---------------------------------------------------------------------------
// Kernel 1: index decode (int64 vs int32) + bucket tokens + zero g_shrunk.
// ---------------------------------------------------------------------------
__global__ void bucket_kernel(const int* __restrict__ raw) {
    __shared__ int bad;
    __shared__ int s_cnt[L_DIM];
    __shared__ int s_base[L_DIM];
    const int tid = threadIdx.x;
    if (tid == 0) bad = 0;
    if (tid < L_DIM) s_cnt[tid] = 0;
    __syncthreads();
    {   // 256 pairs = 2048 bytes, in-bounds for either width
        int lo = raw[2 * tid], hi = raw[2 * tid + 1];
        bool ok = (hi == 0 && lo >= 0) || (hi == -1 && lo < 0);
        if (!ok) bad = 1;
    }
    __syncthreads();
    const bool is64 = (bad == 0);
    for (int t = tid; t < T_DIM; t += 256) {
        int v = is64 ? raw[2 * t] : raw[t];
        g_idx32[t] = v;
        if (v >= 0) atomicAdd(&s_cnt[v], 1);
    }
    for (int i = tid; i < T_DIM * R_DIM / 4; i += 256)
        ((float4*)g_shrunk)[i] = make_float4(0, 0, 0, 0);
    __syncthreads();
    if (tid == 0) {
        int a = 0;
        for (int l = 0; l < L_DIM; l++) { s_base[l] = a; a += s_cnt[l]; }
    }
    __syncthreads();
    if (tid < L_DIM) {
        g_cnt[tid] = s_cnt[tid];
        g_base[tid] = s_base[tid];
        s_cnt[tid] = 0;
    }
    __syncthreads();
    for (int t = tid; t < T_DIM; t += 256) {
        int v = g_idx32[t];
        if (v >= 0) {
            int p = atomicAdd(&s_cnt[v], 1);
            g_tok[s_base[v] + p] = t;
        }
    }
}

// ---------------------------------------------------------------------------
// Kernel 2a: fp32 -> fp16 of X
// ---------------------------------------------------------------------------
__global__ void convert_x(const float* __restrict__ src) {
    int i = blockIdx.x * blockDim.x + threadIdx.x;
    if (i >= T_DIM * H_DIM / 4) return;
    float4 v = ((const float4*)src)[i];
    uint2 ph;
    ph.x = ((uint32_t)__half_as_ushort(__float2half(v.y)) << 16) |
           __half_as_ushort(__float2half(v.x));
    ph.y = ((uint32_t)__half_as_ushort(__float2half(v.w)) << 16) |
           __half_as_ushort(__float2half(v.z));
    ((uint2*)g_Xhi)[i] = ph;
}

// ---------------------------------------------------------------------------
// Kernel 2b: fp32 -> fp16 of W
// ---------------------------------------------------------------------------
__global__ void convert_w(const float* __restrict__ src) {
    int i = blockIdx.x * blockDim.x + threadIdx.x;
    if (i >= O_DIM * H_DIM / 4) return;
    float4 v = ((const float4*)src)[i];
    uint2 ph;
    ph.x = ((uint32_t)__half_as_ushort(__float2half(v.y)) << 16) |
           __half_as_ushort(__float2half(v.x));
    ph.y = ((uint32_t)__half_as_ushort(__float2half(v.w)) << 16) |
           __half_as_ushort(__float2half(v.z));
    ((uint2*)g_Whi)[i] = ph;
}

// ---------------------------------------------------------------------------
// Kernel 3: LoRA shrink, grid (32 adapters, 8 H-chunks, 8 token-slices).
// ---------------------------------------------------------------------------
__global__ __launch_bounds__(256) void shrink3(
    const float* __restrict__ x, const float* __restrict__ lora_a) {
    __shared__ float4 sA4[R_DIM * CHUNK4];       // 16 x 128 float4 = 32 KB
    const int l = blockIdx.x;
    const int n = g_cnt[l];
    if (n == 0) return;
    const int tid = threadIdx.x;
    const int wid = tid >> 5, lid = tid & 31;
    const int slot = blockIdx.z * 8 + wid;       // 0..SH_Z*8-1
    if (blockIdx.z * 8 >= n) return;             // whole block idle -> skip
    const int hb4 = blockIdx.y * CHUNK4;

    const float4* a4 = ((const float4*)lora_a) + (size_t)l * R_DIM * (H_DIM / 4);
    for (int i = tid; i < R_DIM * CHUNK4; i += 256) {
        int r = i / CHUNK4, j4 = i % CHUNK4;
        sA4[i] = a4[r * (H_DIM / 4) + hb4 + j4];
    }
    __syncthreads();

    const int base = g_base[l];
    for (int ti = slot; ti < n; ti += SH_Z * 8) {
        const int t = g_tok[base + ti];
        const float4* x4 = ((const float4*)x) + (size_t)t * (H_DIM / 4) + hb4;
        float4 xv[4];
#pragma unroll
        for (int j = 0; j < 4; j++) xv[j] = x4[lid + 32 * j];
        float acc[R_DIM];
#pragma unroll
        for (int r = 0; r < R_DIM; r++) acc[r] = 0.0f;
#pragma unroll
        for (int j = 0; j < 4; j++) {
#pragma unroll
            for (int r = 0; r < R_DIM; r++) {
                float4 av = sA4[r * CHUNK4 + lid + 32 * j];
                acc[r] += xv[j].x * av.x + xv[j].y * av.y +
                          xv[j].z * av.z + xv[j].w * av.w;
            }
        }
#pragma unroll
        for (int r = 0; r < R_DIM; r++) {
            float v = acc[r];
#pragma unroll
            for (int off = 16; off > 0; off >>= 1)
                v += __shfl_down_sync(0xffffffff, v, off);
            if (lid == 0) atomicAdd(&g_shrunk[t * R_DIM + r], v);
        }
    }
}

// ---------------------------------------------------------------------------
// Kernel 3b: LoRA expand: g_lora[t, c] = shrunk[t,:] . B[l, c, :]
//   grid (32 adapters, 8 col-chunks of 512, 4 token-slices).
//   Thread owns 2 cols of B in registers; token loop strides EX_Z.
// ---------------------------------------------------------------------------
__global__ __launch_bounds__(256) void expand_kernel(
    const float* __restrict__ lora_b) {
    const int l = blockIdx.x;
    const int n = g_cnt[l];
    const int z = blockIdx.z;
    if (z >= n) return;
    const int c0 = blockIdx.y * 512 + threadIdx.x * 2;

    const float4* b0 = (const float4*)(lora_b + ((size_t)l * O_DIM + c0) * R_DIM);
    const float4* b1 = (const float4*)(lora_b + ((size_t)l * O_DIM + c0 + 1) * R_DIM);
    float4 B0[4], B1[4];
#pragma unroll
    for (int q = 0; q < 4; q++) { B0[q] = b0[q]; B1[q] = b1[q]; }

    const int base = g_base[l];
    for (int ti = z; ti < n; ti += EX_Z) {
        const int t = g_tok[base + ti];
        const float4* s4 = (const float4*)(g_shrunk + t * R_DIM);
        float d0 = 0.0f, d1 = 0.0f;
#pragma unroll
        for (int q = 0; q < 4; q++) {
            float4 s = s4[q];
            d0 += s.x * B0[q].x + s.y * B0[q].y + s.z * B0[q].z + s.w * B0[q].w;
            d1 += s.x * B1[q].x + s.y * B1[q].y + s.z * B1[q].z + s.w * B1[q].w;
        }
        *(__half2*)(g_lora + (size_t)t * O_DIM + c0) = __floats2half2_rn(d0, d1);
    }
}

// ---------------------------------------------------------------------------
// Kernel 4: fp16 HMMA GEMM, single product + lightweight epilogue
//   (bias + precomputed fp16 LoRA term). 128x128x32, 4-stage cp.async, occ 2.
// ---------------------------------------------------------------------------
__global__ void __launch_bounds__(256, 2) gemm_hmma(
    const float* __restrict__ bias, float* __restrict__ out) {
    extern __shared__ char dynsmem[];
    const uint32_t sbase = smem_u32(dynsmem);
    const int tid = threadIdx.x;
    const int wid = tid >> 5, lid = tid & 31;
    const int m0 = blockIdx.y * BM, n0 = blockIdx.x * BN;
    const int warp_m = wid & 1;
    const int warp_n = wid >> 1;

    const __half* gsrc[4];
    uint32_t sdst[4];
    {
        const __half* bases[2] = {
            g_Xhi + (size_t)m0 * H_DIM, g_Whi + (size_t)n0 * H_DIM};
#pragma unroll
        for (int i = 0; i < 4; i++) {
            int c = tid + 256 * i;
            int mat = c >> 9, w = c & 511, row = w >> 2, cq = w & 3;
            gsrc[i] = bases[mat] + (size_t)row * H_DIM + cq * 8;
            sdst[i] = mat * MAT_BYTES + swz((uint32_t)(row * 64 + cq * 16));
        }
    }

#pragma unroll
    for (int s = 0; s < STAGES - 1; s++) {
        uint32_t sb = sbase + s * STAGE_BYTES;
#pragma unroll
        for (int i = 0; i < 4; i++) CP_ASYNC16(sb + sdst[i], gsrc[i] + s * BK);
        CP_COMMIT();
    }

    float acc[4][4][4];
#pragma unroll
    for (int a = 0; a < 4; a++)
#pragma unroll
        for (int b = 0; b < 4; b++)
#pragma unroll
            for (int c = 0; c < 4; c++) acc[a][b][c] = 0.0f;

    const uint32_t a_row = warp_m * 64 + (lid & 15);
    const uint32_t a_kb  = ((lid >> 4) & 1) * 16;
    const uint32_t b_row = warp_n * 32 + ((lid >> 4) & 1) * 8 + (lid & 7);
    const uint32_t b_kb  = ((lid >> 3) & 1) * 16;

#pragma unroll 1
    for (int kt = 0; kt < KT_N; kt++) {
        CP_WAIT2();
        __syncthreads();
        const int nt = kt + STAGES - 1;
        if (nt < KT_N) {
            uint32_t sb = sbase + (nt & 3) * STAGE_BYTES;
#pragma unroll
            for (int i = 0; i < 4; i++) CP_ASYNC16(sb + sdst[i], gsrc[i] + nt * BK);
        }
        CP_COMMIT();

        const uint32_t st = sbase + (kt & 3) * STAGE_BYTES;
#pragma unroll
        for (int kk = 0; kk < 2; kk++) {
            const uint32_t koff = kk * 32;
            uint32_t bh[2][4];
#pragma unroll
            for (int nj2 = 0; nj2 < 2; nj2++) {
                uint32_t o = swz((b_row + nj2 * 16) * 64 + koff + b_kb);
                LDSM4(bh[nj2][0], bh[nj2][1], bh[nj2][2], bh[nj2][3],
                      st + MAT_BYTES + o);
            }
#pragma unroll
            for (int mi = 0; mi < 4; mi++) {
                uint32_t ah[4];
                uint32_t o = swz((a_row + mi * 16) * 64 + koff + a_kb);
                LDSM4(ah[0], ah[1], ah[2], ah[3], st + o);
#pragma unroll
                for (int nj = 0; nj < 4; nj++) {
                    const uint32_t b0 = bh[nj >> 1][2 * (nj & 1)];
                    const uint32_t b1 = bh[nj >> 1][2 * (nj & 1) + 1];
                    mma16816h(acc[mi][nj], ah, b0, b1);
                }
            }
        }
    }

    // ---------------- epilogue: bias + precomputed fp16 LoRA term ----------
    const int l4 = lid >> 2, lq = lid & 3;
    const int colbase = n0 + warp_n * 32 + 2 * lq;   // even
    float2 bia[4];
#pragma unroll
    for (int ni = 0; ni < 4; ni++) {
        bia[ni].x = __ldg(bias + colbase + ni * 8);
        bia[ni].y = __ldg(bias + colbase + ni * 8 + 1);
    }
#pragma unroll
    for (int mi = 0; mi < 4; mi++) {
#pragma unroll
        for (int h = 0; h < 2; h++) {
            const int row = m0 + warp_m * 64 + mi * 16 + h * 8 + l4;
            const int li = g_idx32[row];
            float* orow = out + (size_t)row * O_DIM;
            const __half2* lrow =
                (const __half2*)(g_lora + (size_t)row * O_DIM + colbase);
#pragma unroll
            for (int ni = 0; ni < 4; ni++) {
                const int col = colbase + ni * 8;
                float v0 = acc[mi][ni][h * 2 + 0] + bia[ni].x;
                float v1 = acc[mi][ni][h * 2 + 1] + bia[ni].y;
                if (li >= 0) {
                    __half2 hv = lrow[ni * 4];
                    v0 += __low2float(hv);
                    v1 += __high2float(hv);
                }
                *(float2*)(orow + col) = make_float2(v0, v1);
            }
        }
    }
}

// ---------------------------------------------------------------------------
// Stream/event resources: created LAZILY on first kernel_launch call (after
// the harness has initialized the CUDA context). No static-init CUDA calls.
// First call is the (non-captured) correctness run, so no resource creation
// happens inside graph capture; every call launches the identical work.
// ---------------------------------------------------------------------------
namespace {
struct ForkJoin {
    cudaStream_t s1 = nullptr, s2 = nullptr;
    cudaEvent_t e0 = nullptr, e1 = nullptr, e2 = nullptr;
    bool ok = false;
    ForkJoin() {
        ok = (cudaStreamCreateWithFlags(&s1, cudaStreamNonBlocking) == cudaSuccess) &&
             (cudaStreamCreateWithFlags(&s2, cudaStreamNonBlocking) == cudaSuccess) &&
             (cudaEventCreateWithFlags(&e0, cudaEventDisableTiming) == cudaSuccess) &&
             (cudaEventCreateWithFlags(&e1, cudaEventDisableTiming) == cudaSuccess) &&
             (cudaEventCreateWithFlags(&e2, cudaEventDisableTiming) == cudaSuccess);
    }
};
}

// ---------------------------------------------------------------------------
extern "C" void kernel_launch(void* const* d_in, const int* in_sizes, int n_in,
                              void* d_out, int out_size) {
    const float* x      = (const float*)d_in[0];  // (T, H)
    const float* weight = (const float*)d_in[1];  // (O, H)
    const float* bias   = (const float*)d_in[2];  // (O,)
    const float* lora_a = (const float*)d_in[3];  // (L, R, H)
    const float* lora_b = (const float*)d_in[4];  // (L, O, R)
    const int*   rawidx = (const int*)d_in[5];    // (T,) int32 or int64
    float* out = (float*)d_out;                   // (T, O)

    // lazy one-time resources (constructed after CUDA context exists)
    static ForkJoin fj;

    cudaFuncSetAttribute(gemm_hmma, cudaFuncAttributeMaxDynamicSharedMemorySize,
                         DYN_SMEM);

    const int cx_blocks = (T_DIM * H_DIM / 4 + 255) / 256;
    const int cw_blocks = (O_DIM * H_DIM / 4 + 255) / 256;
    const dim3 sh_grid(L_DIM, SH_CH, SH_Z);
    const dim3 ex_grid(L_DIM, O_DIM / 512, EX_Z);
    const dim3 gm_grid(O_DIM / BN, T_DIM / BM);   // (32, 16)

    if (fj.ok) {
        // convert_w has no dependency on bucket -> fork immediately
        cudaEventRecord(fj.e0, 0);
        cudaStreamWaitEvent(fj.s1, fj.e0, 0);
        convert_w<<<cw_blocks, 256, 0, fj.s1>>>(weight);
        cudaEventRecord(fj.e1, fj.s1);

        // stream 0: bucket, then fork shrink->expand chain onto s2
        bucket_kernel<<<1, 256>>>(rawidx);
        cudaEventRecord(fj.e0, 0);
        cudaStreamWaitEvent(fj.s2, fj.e0, 0);
        shrink3<<<sh_grid, 256, 0, fj.s2>>>(x, lora_a);
        expand_kernel<<<ex_grid, 256, 0, fj.s2>>>(lora_b);
        cudaEventRecord(fj.e2, fj.s2);

        convert_x<<<cx_blocks, 256>>>(x);

        // join
        cudaStreamWaitEvent((cudaStream_t)0, fj.e1, 0);
        cudaStreamWaitEvent((cudaStream_t)0, fj.e2, 0);
    } else {
        convert_w<<<cw_blocks, 256>>>(weight);
        bucket_kernel<<<1, 256>>>(rawidx);
        shrink3<<<sh_grid, 256>>>(x, lora_a);
        expand_kernel<<<ex_grid, 256>>>(lora_b);
        convert_x<<<cx_blocks, 256>>>(x);
    }

    gemm_hmma<<<gm_grid, 256, DYN_SMEM>>>(bias, out);
}

// round 11
// speedup vs baseline: 5.9776x; 1.0171x over previous
#include <cuda_runtime.h>
#include <cuda_fp16.h>
#include <cstdint>

#define T_DIM 2048
#define H_DIM 4096
#define O_DIM 4096
#define L_DIM 32
#define R_DIM 16

#define BM 128
#define BN 64
#define BK 32
#define KT_N (H_DIM / BK)          // 128 k-tiles
#define STAGES 4
#define MAT_A_BYTES 8192           // 128 rows x 64 bytes
#define MAT_B_BYTES 4096           // 64 rows x 64 bytes
#define STAGE_BYTES (MAT_A_BYTES + MAT_B_BYTES)   // 12 KB
#define DYN_SMEM (STAGES * STAGE_BYTES)           // 48 KB

#define SH_CH 8                    // shrink H-chunks
#define SH_Z 8                     // shrink token-split
#define CHUNK4 (H_DIM / 4 / SH_CH) // 128 float4 per chunk
#define EX_Z 8                     // expand token-split

// ---------------- device scratch ----------------
__device__ int    g_idx32[T_DIM];
__device__ int    g_tok[T_DIM];
__device__ int    g_cnt[L_DIM];
__device__ int    g_base[L_DIM];
__device__ float  g_shrunk[T_DIM * R_DIM];
__device__ __half g_lora[(size_t)T_DIM * O_DIM];   // fp16 LoRA contribution
__device__ __half g_Xhi[T_DIM * H_DIM];
__device__ __half g_Whi[O_DIM * H_DIM];

// ---------------- helpers ----------------
__device__ __forceinline__ uint32_t smem_u32(const void* p) {
    uint32_t a;
    asm("{ .reg .u64 t; cvta.to.shared.u64 t, %1; cvt.u32.u64 %0, t; }"
        : "=r"(a) : "l"(p));
    return a;
}

__device__ __forceinline__ uint32_t swz(uint32_t o) {
    return o ^ ((o >> 3) & 0x30);   // 64B-row swizzle
}

#define CP_ASYNC16(dst, src) \
    asm volatile("cp.async.cg.shared.global [%0], [%1], 16;" :: "r"(dst), "l"(src))
#define CP_COMMIT() asm volatile("cp.async.commit_group;" ::: "memory")
#define CP_WAIT2()  asm volatile("cp.async.wait_group 2;" ::: "memory")

#define LDSM4(d0, d1, d2, d3, a)                                          \
    asm volatile("ldmatrix.sync.aligned.m8n8.x4.shared.b16 {%0,%1,%2,%3}, [%4];" \
                 : "=r"(d0), "=r"(d1), "=r"(d2), "=r"(d3) : "r"(a))

__device__ __forceinline__ void mma16816h(float* c, const uint32_t* a,
                                          uint32_t b0, uint32_t b1) {
    asm volatile(
        "mma.sync.aligned.m16n8k16.row.col.f32.f16.f16.f32 "
        "{%0,%1,%2,%3}, {%4,%5,%6,%7}, {%8,%9}, {%0,%1,%2,%3};"
        : "+f"(c[0]), "+f"(c[1]), "+f"(c[2]), "+f"(c[3])
        : "r"(a[0]), "r"(a[1]), "r"(a[2]), "r"(a[3]), "r"(b0), "r"(b1));
}

// ---------------------------------------------------------------------------
// Kernel 1: index decode (int64 vs int32) + bucket tokens + zero g_shrunk.
// ---------------------------------------------------------------------------
__global__ void bucket_kernel(const int* __restrict__ raw) {
    __shared__ int bad;
    __shared__ int s_cnt[L_DIM];
    __shared__ int s_base[L_DIM];
    const int tid = threadIdx.x;
    if (tid == 0) bad = 0;
    if (tid < L_DIM) s_cnt[tid] = 0;
    __syncthreads();
    {   // 256 pairs = 2048 bytes, in-bounds for either width
        int lo = raw[2 * tid], hi = raw[2 * tid + 1];
        bool ok = (hi == 0 && lo >= 0) || (hi == -1 && lo < 0);
        if (!ok) bad = 1;
    }
    __syncthreads();
    const bool is64 = (bad == 0);
    for (int t = tid; t < T_DIM; t += 256) {
        int v = is64 ? raw[2 * t] : raw[t];
        g_idx32[t] = v;
        if (v >= 0) atomicAdd(&s_cnt[v], 1);
    }
    for (int i = tid; i < T_DIM * R_DIM / 4; i += 256)
        ((float4*)g_shrunk)[i] = make_float4(0, 0, 0, 0);
    __syncthreads();
    if (tid == 0) {
        int a = 0;
        for (int l = 0; l < L_DIM; l++) { s_base[l] = a; a += s_cnt[l]; }
    }
    __syncthreads();
    if (tid < L_DIM) {
        g_cnt[tid] = s_cnt[tid];
        g_base[tid] = s_base[tid];
        s_cnt[tid] = 0;
    }
    __syncthreads();
    for (int t = tid; t < T_DIM; t += 256) {
        int v = g_idx32[t];
        if (v >= 0) {
            int p = atomicAdd(&s_cnt[v], 1);
            g_tok[s_base[v] + p] = t;
        }
    }
}

// ---------------------------------------------------------------------------
// Kernel 2a: fp32 -> fp16 of X
// ---------------------------------------------------------------------------
__global__ void convert_x(const float* __restrict__ src) {
    int i = blockIdx.x * blockDim.x + threadIdx.x;
    if (i >= T_DIM * H_DIM / 4) return;
    float4 v = ((const float4*)src)[i];
    uint2 ph;
    ph.x = ((uint32_t)__half_as_ushort(__float2half(v.y)) << 16) |
           __half_as_ushort(__float2half(v.x));
    ph.y = ((uint32_t)__half_as_ushort(__float2half(v.w)) << 16) |
           __half_as_ushort(__float2half(v.z));
    ((uint2*)g_Xhi)[i] = ph;
}

// ---------------------------------------------------------------------------
// Kernel 2b: fp32 -> fp16 of W
// ---------------------------------------------------------------------------
__global__ void convert_w(const float* __restrict__ src) {
    int i = blockIdx.x * blockDim.x + threadIdx.x;
    if (i >= O_DIM * H_DIM / 4) return;
    float4 v = ((const float4*)src)[i];
    uint2 ph;
    ph.x = ((uint32_t)__half_as_ushort(__float2half(v.y)) << 16) |
           __half_as_ushort(__float2half(v.x));
    ph.y = ((uint32_t)__half_as_ushort(__float2half(v.w)) << 16) |
           __half_as_ushort(__float2half(v.z));
    ((uint2*)g_Whi)[i] = ph;
}

// ---------------------------------------------------------------------------
// Kernel 3: LoRA shrink, grid (32 adapters, 8 H-chunks, 8 token-slices).
// ---------------------------------------------------------------------------
__global__ __launch_bounds__(256) void shrink3(
    const float* __restrict__ x, const float* __restrict__ lora_a) {
    __shared__ float4 sA4[R_DIM * CHUNK4];       // 16 x 128 float4 = 32 KB
    const int l = blockIdx.x;
    const int n = g_cnt[l];
    if (n == 0) return;
    const int tid = threadIdx.x;
    const int wid = tid >> 5, lid = tid & 31;
    const int slot = blockIdx.z * 8 + wid;       // 0..SH_Z*8-1
    if (blockIdx.z * 8 >= n) return;             // whole block idle -> skip
    const int hb4 = blockIdx.y * CHUNK4;

    const float4* a4 = ((const float4*)lora_a) + (size_t)l * R_DIM * (H_DIM / 4);
    for (int i = tid; i < R_DIM * CHUNK4; i += 256) {
        int r = i / CHUNK4, j4 = i % CHUNK4;
        sA4[i] = a4[r * (H_DIM / 4) + hb4 + j4];
    }
    __syncthreads();

    const int base = g_base[l];
    for (int ti = slot; ti < n; ti += SH_Z * 8) {
        const int t = g_tok[base + ti];
        const float4* x4 = ((const float4*)x) + (size_t)t * (H_DIM / 4) + hb4;
        float4 xv[4];
#pragma unroll
        for (int j = 0; j < 4; j++) xv[j] = x4[lid + 32 * j];
        float acc[R_DIM];
#pragma unroll
        for (int r = 0; r < R_DIM; r++) acc[r] = 0.0f;
#pragma unroll
        for (int j = 0; j < 4; j++) {
#pragma unroll
            for (int r = 0; r < R_DIM; r++) {
                float4 av = sA4[r * CHUNK4 + lid + 32 * j];
                acc[r] += xv[j].x * av.x + xv[j].y * av.y +
                          xv[j].z * av.z + xv[j].w * av.w;
            }
        }
#pragma unroll
        for (int r = 0; r < R_DIM; r++) {
            float v = acc[r];
#pragma unroll
            for (int off = 16; off > 0; off >>= 1)
                v += __shfl_down_sync(0xffffffff, v, off);
            if (lid == 0) atomicAdd(&g_shrunk[t * R_DIM + r], v);
        }
    }
}

// ---------------------------------------------------------------------------
// Kernel 3b: LoRA expand: g_lora[t, c] = shrunk[t,:] . B[l, c, :]
//   grid (32 adapters, 8 col-chunks of 512, 8 token-slices).
//   4 independent 8-FMA chains per token for ILP.
// ---------------------------------------------------------------------------
__global__ __launch_bounds__(256) void expand_kernel(
    const float* __restrict__ lora_b) {
    const int l = blockIdx.x;
    const int n = g_cnt[l];
    const int z = blockIdx.z;
    if (z >= n) return;
    const int c0 = blockIdx.y * 512 + threadIdx.x * 2;

    const float4* b0 = (const float4*)(lora_b + ((size_t)l * O_DIM + c0) * R_DIM);
    const float4* b1 = (const float4*)(lora_b + ((size_t)l * O_DIM + c0 + 1) * R_DIM);
    float4 B0[4], B1[4];
#pragma unroll
    for (int q = 0; q < 4; q++) { B0[q] = b0[q]; B1[q] = b1[q]; }

    const int base = g_base[l];
    for (int ti = z; ti < n; ti += EX_Z) {
        const int t = g_tok[base + ti];
        const float4* s4 = (const float4*)(g_shrunk + t * R_DIM);
        float4 s0 = s4[0], s1 = s4[1], s2 = s4[2], s3 = s4[3];
        // split accumulation: 4 independent chains (2 per output col)
        float d0a = s0.x * B0[0].x + s0.y * B0[0].y + s0.z * B0[0].z + s0.w * B0[0].w;
        float d0b = s1.x * B0[1].x + s1.y * B0[1].y + s1.z * B0[1].z + s1.w * B0[1].w;
        float d1a = s0.x * B1[0].x + s0.y * B1[0].y + s0.z * B1[0].z + s0.w * B1[0].w;
        float d1b = s1.x * B1[1].x + s1.y * B1[1].y + s1.z * B1[1].z + s1.w * B1[1].w;
        d0a += s2.x * B0[2].x + s2.y * B0[2].y + s2.z * B0[2].z + s2.w * B0[2].w;
        d0b += s3.x * B0[3].x + s3.y * B0[3].y + s3.z * B0[3].z + s3.w * B0[3].w;
        d1a += s2.x * B1[2].x + s2.y * B1[2].y + s2.z * B1[2].z + s2.w * B1[2].w;
        d1b += s3.x * B1[3].x + s3.y * B1[3].y + s3.z * B1[3].z + s3.w * B1[3].w;
        *(__half2*)(g_lora + (size_t)t * O_DIM + c0) =
            __floats2half2_rn(d0a + d0b, d1a + d1b);
    }
}

// ---------------------------------------------------------------------------
// Kernel 4: fp16 HMMA GEMM, single product + lightweight epilogue.
//   128x64 tiles (1024 tiles -> 98.8% SM packing), 4-stage cp.async, occ 3.
//   8 warps: warp_m = wid&3 (32-row band), warp_n = wid>>2 (32-col band).
// ---------------------------------------------------------------------------
__global__ void __launch_bounds__(256, 3) gemm_hmma(
    const float* __restrict__ bias, float* __restrict__ out) {
    extern __shared__ char dynsmem[];
    const uint32_t sbase = smem_u32(dynsmem);
    const int tid = threadIdx.x;
    const int wid = tid >> 5, lid = tid & 31;
    const int m0 = blockIdx.y * BM, n0 = blockIdx.x * BN;
    const int warp_m = wid & 3;        // 0..3 -> 32-row bands
    const int warp_n = wid >> 2;       // 0..1 -> 32-col bands

    // loader precompute: 3 x 16B per thread per stage (A: 512 chunks, B: 256)
    const __half* gsrc[3];
    uint32_t sdst[3];
    {
        const __half* baseA = g_Xhi + (size_t)m0 * H_DIM;
        const __half* baseB = g_Whi + (size_t)n0 * H_DIM;
#pragma unroll
        for (int i = 0; i < 3; i++) {
            int c = tid + 256 * i;
            int mat = (c >= 512);
            int w = mat ? (c - 512) : c;
            int row = w >> 2, cq = w & 3;
            gsrc[i] = (mat ? baseB : baseA) + (size_t)row * H_DIM + cq * 8;
            sdst[i] = (mat ? MAT_A_BYTES : 0) + swz((uint32_t)(row * 64 + cq * 16));
        }
    }

#pragma unroll
    for (int s = 0; s < STAGES - 1; s++) {
        uint32_t sb = sbase + s * STAGE_BYTES;
#pragma unroll
        for (int i = 0; i < 3; i++) CP_ASYNC16(sb + sdst[i], gsrc[i] + s * BK);
        CP_COMMIT();
    }

    float acc[2][4][4];
#pragma unroll
    for (int a = 0; a < 2; a++)
#pragma unroll
        for (int b = 0; b < 4; b++)
#pragma unroll
            for (int c = 0; c < 4; c++) acc[a][b][c] = 0.0f;

    const uint32_t a_row = warp_m * 32 + (lid & 15);
    const uint32_t a_kb  = ((lid >> 4) & 1) * 16;
    const uint32_t b_row = warp_n * 32 + ((lid >> 4) & 1) * 8 + (lid & 7);
    const uint32_t b_kb  = ((lid >> 3) & 1) * 16;

#pragma unroll 1
    for (int kt = 0; kt < KT_N; kt++) {
        CP_WAIT2();
        __syncthreads();
        const int nt = kt + STAGES - 1;
        if (nt < KT_N) {
            uint32_t sb = sbase + (nt & 3) * STAGE_BYTES;
#pragma unroll
            for (int i = 0; i < 3; i++) CP_ASYNC16(sb + sdst[i], gsrc[i] + nt * BK);
        }
        CP_COMMIT();

        const uint32_t st = sbase + (kt & 3) * STAGE_BYTES;
#pragma unroll
        for (int kk = 0; kk < 2; kk++) {
            const uint32_t koff = kk * 32;
            uint32_t bh[2][4];
#pragma unroll
            for (int nj2 = 0; nj2 < 2; nj2++) {
                uint32_t o = swz((b_row + nj2 * 16) * 64 + koff + b_kb);
                LDSM4(bh[nj2][0], bh[nj2][1], bh[nj2][2], bh[nj2][3],
                      st + MAT_A_BYTES + o);
            }
#pragma unroll
            for (int mi = 0; mi < 2; mi++) {
                uint32_t ah[4];
                uint32_t o = swz((a_row + mi * 16) * 64 + koff + a_kb);
                LDSM4(ah[0], ah[1], ah[2], ah[3], st + o);
#pragma unroll
                for (int nj = 0; nj < 4; nj++) {
                    const uint32_t b0 = bh[nj >> 1][2 * (nj & 1)];
                    const uint32_t b1 = bh[nj >> 1][2 * (nj & 1) + 1];
                    mma16816h(acc[mi][nj], ah, b0, b1);
                }
            }
        }
    }

    // ---------------- epilogue: bias + precomputed fp16 LoRA term ----------
    const int l4 = lid >> 2, lq = lid & 3;
    const int colbase = n0 + warp_n * 32 + 2 * lq;   // even
    float2 bia[4];
#pragma unroll
    for (int ni = 0; ni < 4; ni++) {
        bia[ni].x = __ldg(bias + colbase + ni * 8);
        bia[ni].y = __ldg(bias + colbase + ni * 8 + 1);
    }
#pragma unroll
    for (int mi = 0; mi < 2; mi++) {
#pragma unroll
        for (int h = 0; h < 2; h++) {
            const int row = m0 + warp_m * 32 + mi * 16 + h * 8 + l4;
            const int li = g_idx32[row];
            float* orow = out + (size_t)row * O_DIM;
            const __half2* lrow =
                (const __half2*)(g_lora + (size_t)row * O_DIM + colbase);
#pragma unroll
            for (int ni = 0; ni < 4; ni++) {
                const int col = colbase + ni * 8;
                float v0 = acc[mi][ni][h * 2 + 0] + bia[ni].x;
                float v1 = acc[mi][ni][h * 2 + 1] + bia[ni].y;
                if (li >= 0) {
                    __half2 hv = lrow[ni * 4];
                    v0 += __low2float(hv);
                    v1 += __high2float(hv);
                }
                *(float2*)(orow + col) = make_float2(v0, v1);
            }
        }
    }
}

// ---------------------------------------------------------------------------
// Stream/event resources: created LAZILY on first kernel_launch call (after
// the harness has initialized the CUDA context). No static-init CUDA calls.
// ---------------------------------------------------------------------------
namespace {
struct ForkJoin {
    cudaStream_t s1 = nullptr, s2 = nullptr;
    cudaEvent_t e0 = nullptr, e1 = nullptr, e2 = nullptr;
    bool ok = false;
    ForkJoin() {
        ok = (cudaStreamCreateWithFlags(&s1, cudaStreamNonBlocking) == cudaSuccess) &&
             (cudaStreamCreateWithFlags(&s2, cudaStreamNonBlocking) == cudaSuccess) &&
             (cudaEventCreateWithFlags(&e0, cudaEventDisableTiming) == cudaSuccess) &&
             (cudaEventCreateWithFlags(&e1, cudaEventDisableTiming) == cudaSuccess) &&
             (cudaEventCreateWithFlags(&e2, cudaEventDisableTiming) == cudaSuccess);
    }
};
}

// ---------------------------------------------------------------------------
extern "C" void kernel_launch(void* const* d_in, const int* in_sizes, int n_in,
                              void* d_out, int out_size) {
    const float* x      = (const float*)d_in[0];  // (T, H)
    const float* weight = (const float*)d_in[1];  // (O, H)
    const float* bias   = (const float*)d_in[2];  // (O,)
    const float* lora_a = (const float*)d_in[3];  // (L, R, H)
    const float* lora_b = (const float*)d_in[4];  // (L, O, R)
    const int*   rawidx = (const int*)d_in[5];    // (T,) int32 or int64
    float* out = (float*)d_out;                   // (T, O)

    // lazy one-time resources (constructed after CUDA context exists)
    static ForkJoin fj;

    cudaFuncSetAttribute(gemm_hmma, cudaFuncAttributeMaxDynamicSharedMemorySize,
                         DYN_SMEM);

    const int cx_blocks = (T_DIM * H_DIM / 4 + 255) / 256;
    const int cw_blocks = (O_DIM * H_DIM / 4 + 255) / 256;
    const dim3 sh_grid(L_DIM, SH_CH, SH_Z);
    const dim3 ex_grid(L_DIM, O_DIM / 512, EX_Z);
    const dim3 gm_grid(O_DIM / BN, T_DIM / BM);   // (64, 16) = 1024 tiles

    if (fj.ok) {
        // convert_w has no dependency on bucket -> fork immediately
        cudaEventRecord(fj.e0, 0);
        cudaStreamWaitEvent(fj.s1, fj.e0, 0);
        convert_w<<<cw_blocks, 256, 0, fj.s1>>>(weight);
        cudaEventRecord(fj.e1, fj.s1);

        // stream 0: bucket, then fork shrink->expand chain onto s2
        bucket_kernel<<<1, 256>>>(rawidx);
        cudaEventRecord(fj.e0, 0);
        cudaStreamWaitEvent(fj.s2, fj.e0, 0);
        shrink3<<<sh_grid, 256, 0, fj.s2>>>(x, lora_a);
        expand_kernel<<<ex_grid, 256, 0, fj.s2>>>(lora_b);
        cudaEventRecord(fj.e2, fj.s2);

        convert_x<<<cx_blocks, 256>>>(x);

        // join
        cudaStreamWaitEvent((cudaStream_t)0, fj.e1, 0);
        cudaStreamWaitEvent((cudaStream_t)0, fj.e2, 0);
    } else {
        convert_w<<<cw_blocks, 256>>>(weight);
        bucket_kernel<<<1, 256>>>(rawidx);
        shrink3<<<sh_grid, 256>>>(x, lora_a);
        expand_kernel<<<ex_grid, 256>>>(lora_b);
        convert_x<<<cx_blocks, 256>>>(x);
    }

    gemm_hmma<<<gm_grid, 256, DYN_SMEM>>>(bias, out);
}

// round 12
// speedup vs baseline: 6.1348x; 1.0263x over previous
#include <cuda_runtime.h>
#include <cuda_fp16.h>
#include <cstdint>

#define T_DIM 2048
#define H_DIM 4096
#define O_DIM 4096
#define L_DIM 32
#define R_DIM 16

#define BM 128
#define BN 64
#define BK 32
#define KT_N (H_DIM / BK)          // 128 k-tiles
#define STAGES 4
#define MAT_A_BYTES 8192           // 128 rows x 64 bytes
#define MAT_B_BYTES 4096           // 64 rows x 64 bytes
#define STAGE_BYTES (MAT_A_BYTES + MAT_B_BYTES)   // 12 KB
#define DYN_SMEM (STAGES * STAGE_BYTES)           // 48 KB

#define SH_CH 8                    // shrink H-chunks
#define SH_Z 8                     // shrink token-split
#define CHUNK4 (H_DIM / 4 / SH_CH) // 128 float4 per chunk
#define EX_Z 8                     // expand token-split
#define EX_CHUNK 32                // staged tokens per round

// ---------------- device scratch ----------------
__device__ int    g_idx32[T_DIM];
__device__ int    g_tok[T_DIM];
__device__ int    g_cnt[L_DIM];
__device__ int    g_base[L_DIM];
__device__ float  g_shrunk[T_DIM * R_DIM];
__device__ __half g_lora[(size_t)T_DIM * O_DIM];   // fp16 LoRA contribution
__device__ __half g_Xhi[T_DIM * H_DIM];
__device__ __half g_Whi[O_DIM * H_DIM];

// ---------------- helpers ----------------
__device__ __forceinline__ uint32_t smem_u32(const void* p) {
    uint32_t a;
    asm("{ .reg .u64 t; cvta.to.shared.u64 t, %1; cvt.u32.u64 %0, t; }"
        : "=r"(a) : "l"(p));
    return a;
}

__device__ __forceinline__ uint32_t swz(uint32_t o) {
    return o ^ ((o >> 3) & 0x30);   // 64B-row swizzle
}

#define CP_ASYNC16(dst, src) \
    asm volatile("cp.async.cg.shared.global [%0], [%1], 16;" :: "r"(dst), "l"(src))
#define CP_COMMIT() asm volatile("cp.async.commit_group;" ::: "memory")
#define CP_WAIT2()  asm volatile("cp.async.wait_group 2;" ::: "memory")

#define LDSM4(d0, d1, d2, d3, a)                                          \
    asm volatile("ldmatrix.sync.aligned.m8n8.x4.shared.b16 {%0,%1,%2,%3}, [%4];" \
                 : "=r"(d0), "=r"(d1), "=r"(d2), "=r"(d3) : "r"(a))

__device__ __forceinline__ void mma16816h(float* c, const uint32_t* a,
                                          uint32_t b0, uint32_t b1) {
    asm volatile(
        "mma.sync.aligned.m16n8k16.row.col.f32.f16.f16.f32 "
        "{%0,%1,%2,%3}, {%4,%5,%6,%7}, {%8,%9}, {%0,%1,%2,%3};"
        : "+f"(c[0]), "+f"(c[1]), "+f"(c[2]), "+f"(c[3])
        : "r"(a[0]), "r"(a[1]), "r"(a[2]), "r"(a[3]), "r"(b0), "r"(b1));
}

// ---------------------------------------------------------------------------
// Kernel 1: index decode (int64 vs int32) + bucket tokens + zero g_shrunk.
// ---------------------------------------------------------------------------
__global__ void bucket_kernel(const int* __restrict__ raw) {
    __shared__ int bad;
    __shared__ int s_cnt[L_DIM];
    __shared__ int s_base[L_DIM];
    const int tid = threadIdx.x;
    if (tid == 0) bad = 0;
    if (tid < L_DIM) s_cnt[tid] = 0;
    __syncthreads();
    {   // 256 pairs = 2048 bytes, in-bounds for either width
        int lo = raw[2 * tid], hi = raw[2 * tid + 1];
        bool ok = (hi == 0 && lo >= 0) || (hi == -1 && lo < 0);
        if (!ok) bad = 1;
    }
    __syncthreads();
    const bool is64 = (bad == 0);
    for (int t = tid; t < T_DIM; t += 256) {
        int v = is64 ? raw[2 * t] : raw[t];
        g_idx32[t] = v;
        if (v >= 0) atomicAdd(&s_cnt[v], 1);
    }
    for (int i = tid; i < T_DIM * R_DIM / 4; i += 256)
        ((float4*)g_shrunk)[i] = make_float4(0, 0, 0, 0);
    __syncthreads();
    if (tid == 0) {
        int a = 0;
        for (int l = 0; l < L_DIM; l++) { s_base[l] = a; a += s_cnt[l]; }
    }
    __syncthreads();
    if (tid < L_DIM) {
        g_cnt[tid] = s_cnt[tid];
        g_base[tid] = s_base[tid];
        s_cnt[tid] = 0;
    }
    __syncthreads();
    for (int t = tid; t < T_DIM; t += 256) {
        int v = g_idx32[t];
        if (v >= 0) {
            int p = atomicAdd(&s_cnt[v], 1);
            g_tok[s_base[v] + p] = t;
        }
    }
}

// ---------------------------------------------------------------------------
// Kernel 2a: fp32 -> fp16 of X
// ---------------------------------------------------------------------------
__global__ void convert_x(const float* __restrict__ src) {
    int i = blockIdx.x * blockDim.x + threadIdx.x;
    if (i >= T_DIM * H_DIM / 4) return;
    float4 v = ((const float4*)src)[i];
    uint2 ph;
    ph.x = ((uint32_t)__half_as_ushort(__float2half(v.y)) << 16) |
           __half_as_ushort(__float2half(v.x));
    ph.y = ((uint32_t)__half_as_ushort(__float2half(v.w)) << 16) |
           __half_as_ushort(__float2half(v.z));
    ((uint2*)g_Xhi)[i] = ph;
}

// ---------------------------------------------------------------------------
// Kernel 2b: fp32 -> fp16 of W
// ---------------------------------------------------------------------------
__global__ void convert_w(const float* __restrict__ src) {
    int i = blockIdx.x * blockDim.x + threadIdx.x;
    if (i >= O_DIM * H_DIM / 4) return;
    float4 v = ((const float4*)src)[i];
    uint2 ph;
    ph.x = ((uint32_t)__half_as_ushort(__float2half(v.y)) << 16) |
           __half_as_ushort(__float2half(v.x));
    ph.y = ((uint32_t)__half_as_ushort(__float2half(v.w)) << 16) |
           __half_as_ushort(__float2half(v.z));
    ((uint2*)g_Whi)[i] = ph;
}

// ---------------------------------------------------------------------------
// Kernel 3: LoRA shrink, grid (32 adapters, 8 H-chunks, 8 token-slices).
// ---------------------------------------------------------------------------
__global__ __launch_bounds__(256) void shrink3(
    const float* __restrict__ x, const float* __restrict__ lora_a) {
    __shared__ float4 sA4[R_DIM * CHUNK4];       // 16 x 128 float4 = 32 KB
    const int l = blockIdx.x;
    const int n = g_cnt[l];
    if (n == 0) return;
    const int tid = threadIdx.x;
    const int wid = tid >> 5, lid = tid & 31;
    const int slot = blockIdx.z * 8 + wid;       // 0..SH_Z*8-1
    if (blockIdx.z * 8 >= n) return;             // whole block idle -> skip
    const int hb4 = blockIdx.y * CHUNK4;

    const float4* a4 = ((const float4*)lora_a) + (size_t)l * R_DIM * (H_DIM / 4);
    for (int i = tid; i < R_DIM * CHUNK4; i += 256) {
        int r = i / CHUNK4, j4 = i % CHUNK4;
        sA4[i] = a4[r * (H_DIM / 4) + hb4 + j4];
    }
    __syncthreads();

    const int base = g_base[l];
    for (int ti = slot; ti < n; ti += SH_Z * 8) {
        const int t = g_tok[base + ti];
        const float4* x4 = ((const float4*)x) + (size_t)t * (H_DIM / 4) + hb4;
        float4 xv[4];
#pragma unroll
        for (int j = 0; j < 4; j++) xv[j] = x4[lid + 32 * j];
        float acc[R_DIM];
#pragma unroll
        for (int r = 0; r < R_DIM; r++) acc[r] = 0.0f;
#pragma unroll
        for (int j = 0; j < 4; j++) {
#pragma unroll
            for (int r = 0; r < R_DIM; r++) {
                float4 av = sA4[r * CHUNK4 + lid + 32 * j];
                acc[r] += xv[j].x * av.x + xv[j].y * av.y +
                          xv[j].z * av.z + xv[j].w * av.w;
            }
        }
#pragma unroll
        for (int r = 0; r < R_DIM; r++) {
            float v = acc[r];
#pragma unroll
            for (int off = 16; off > 0; off >>= 1)
                v += __shfl_down_sync(0xffffffff, v, off);
            if (lid == 0) atomicAdd(&g_shrunk[t * R_DIM + r], v);
        }
    }
}

// ---------------------------------------------------------------------------
// Kernel 3b: LoRA expand: g_lora[t, c] = shrunk[t,:] . B[l, c, :]
//   grid (32 adapters, 8 col-chunks of 512, 8 token-slices).
//   Slice tokens staged into SMEM (32 at a time) -> per-token work is pure
//   broadcast-LDS + FFMA, no redundant global loads in the hot loop.
// ---------------------------------------------------------------------------
__global__ __launch_bounds__(256) void expand_kernel(
    const float* __restrict__ lora_b) {
    __shared__ float4 sS[EX_CHUNK][4];
    __shared__ int    sT[EX_CHUNK];
    const int l = blockIdx.x;
    const int n = g_cnt[l];
    const int z = blockIdx.z;
    if (z >= n) return;
    const int c0 = blockIdx.y * 512 + threadIdx.x * 2;

    const float4* b0 = (const float4*)(lora_b + ((size_t)l * O_DIM + c0) * R_DIM);
    const float4* b1 = (const float4*)(lora_b + ((size_t)l * O_DIM + c0 + 1) * R_DIM);
    float4 B0[4], B1[4];
#pragma unroll
    for (int q = 0; q < 4; q++) { B0[q] = b0[q]; B1[q] = b1[q]; }

    const int base = g_base[l];
    for (int ck = z; ck < n; ck += EX_Z * EX_CHUNK) {
        int cnt = (n - ck + EX_Z - 1) / EX_Z;
        if (cnt > EX_CHUNK) cnt = EX_CHUNK;
        __syncthreads();                       // prior round's reads done
        if (threadIdx.x < cnt * 4) {
            const int j = threadIdx.x >> 2, q = threadIdx.x & 3;
            const int t = g_tok[base + ck + j * EX_Z];
            if (q == 0) sT[j] = t;
            sS[j][q] = ((const float4*)g_shrunk)[t * 4 + q];
        }
        __syncthreads();
#pragma unroll 2
        for (int j = 0; j < cnt; j++) {
            const int t = sT[j];
            const float4 s0 = sS[j][0], s1 = sS[j][1];
            const float4 s2 = sS[j][2], s3 = sS[j][3];
            float d0a = s0.x * B0[0].x + s0.y * B0[0].y + s0.z * B0[0].z + s0.w * B0[0].w;
            float d0b = s1.x * B0[1].x + s1.y * B0[1].y + s1.z * B0[1].z + s1.w * B0[1].w;
            float d1a = s0.x * B1[0].x + s0.y * B1[0].y + s0.z * B1[0].z + s0.w * B1[0].w;
            float d1b = s1.x * B1[1].x + s1.y * B1[1].y + s1.z * B1[1].z + s1.w * B1[1].w;
            d0a += s2.x * B0[2].x + s2.y * B0[2].y + s2.z * B0[2].z + s2.w * B0[2].w;
            d0b += s3.x * B0[3].x + s3.y * B0[3].y + s3.z * B0[3].z + s3.w * B0[3].w;
            d1a += s2.x * B1[2].x + s2.y * B1[2].y + s2.z * B1[2].z + s2.w * B1[2].w;
            d1b += s3.x * B1[3].x + s3.y * B1[3].y + s3.z * B1[3].z + s3.w * B1[3].w;
            *(__half2*)(g_lora + (size_t)t * O_DIM + c0) =
                __floats2half2_rn(d0a + d0b, d1a + d1b);
        }
    }
}

// ---------------------------------------------------------------------------
// Kernel 4: fp16 HMMA GEMM, single product + lightweight epilogue.
//   128x64 tiles (1024 tiles -> 98.8% SM packing), 4-stage cp.async, occ 3.
// ---------------------------------------------------------------------------
__global__ void __launch_bounds__(256, 3) gemm_hmma(
    const float* __restrict__ bias, float* __restrict__ out) {
    extern __shared__ char dynsmem[];
    const uint32_t sbase = smem_u32(dynsmem);
    const int tid = threadIdx.x;
    const int wid = tid >> 5, lid = tid & 31;
    const int m0 = blockIdx.y * BM, n0 = blockIdx.x * BN;
    const int warp_m = wid & 3;        // 0..3 -> 32-row bands
    const int warp_n = wid >> 2;       // 0..1 -> 32-col bands

    const __half* gsrc[3];
    uint32_t sdst[3];
    {
        const __half* baseA = g_Xhi + (size_t)m0 * H_DIM;
        const __half* baseB = g_Whi + (size_t)n0 * H_DIM;
#pragma unroll
        for (int i = 0; i < 3; i++) {
            int c = tid + 256 * i;
            int mat = (c >= 512);
            int w = mat ? (c - 512) : c;
            int row = w >> 2, cq = w & 3;
            gsrc[i] = (mat ? baseB : baseA) + (size_t)row * H_DIM + cq * 8;
            sdst[i] = (mat ? MAT_A_BYTES : 0) + swz((uint32_t)(row * 64 + cq * 16));
        }
    }

#pragma unroll
    for (int s = 0; s < STAGES - 1; s++) {
        uint32_t sb = sbase + s * STAGE_BYTES;
#pragma unroll
        for (int i = 0; i < 3; i++) CP_ASYNC16(sb + sdst[i], gsrc[i] + s * BK);
        CP_COMMIT();
    }

    float acc[2][4][4];
#pragma unroll
    for (int a = 0; a < 2; a++)
#pragma unroll
        for (int b = 0; b < 4; b++)
#pragma unroll
            for (int c = 0; c < 4; c++) acc[a][b][c] = 0.0f;

    const uint32_t a_row = warp_m * 32 + (lid & 15);
    const uint32_t a_kb  = ((lid >> 4) & 1) * 16;
    const uint32_t b_row = warp_n * 32 + ((lid >> 4) & 1) * 8 + (lid & 7);
    const uint32_t b_kb  = ((lid >> 3) & 1) * 16;

#pragma unroll 1
    for (int kt = 0; kt < KT_N; kt++) {
        CP_WAIT2();
        __syncthreads();
        const int nt = kt + STAGES - 1;
        if (nt < KT_N) {
            uint32_t sb = sbase + (nt & 3) * STAGE_BYTES;
#pragma unroll
            for (int i = 0; i < 3; i++) CP_ASYNC16(sb + sdst[i], gsrc[i] + nt * BK);
        }
        CP_COMMIT();

        const uint32_t st = sbase + (kt & 3) * STAGE_BYTES;
#pragma unroll
        for (int kk = 0; kk < 2; kk++) {
            const uint32_t koff = kk * 32;
            uint32_t bh[2][4];
#pragma unroll
            for (int nj2 = 0; nj2 < 2; nj2++) {
                uint32_t o = swz((b_row + nj2 * 16) * 64 + koff + b_kb);
                LDSM4(bh[nj2][0], bh[nj2][1], bh[nj2][2], bh[nj2][3],
                      st + MAT_A_BYTES + o);
            }
#pragma unroll
            for (int mi = 0; mi < 2; mi++) {
                uint32_t ah[4];
                uint32_t o = swz((a_row + mi * 16) * 64 + koff + a_kb);
                LDSM4(ah[0], ah[1], ah[2], ah[3], st + o);
#pragma unroll
                for (int nj = 0; nj < 4; nj++) {
                    const uint32_t b0 = bh[nj >> 1][2 * (nj & 1)];
                    const uint32_t b1 = bh[nj >> 1][2 * (nj & 1) + 1];
                    mma16816h(acc[mi][nj], ah, b0, b1);
                }
            }
        }
    }

    // ---------------- epilogue: bias + precomputed fp16 LoRA term ----------
    const int l4 = lid >> 2, lq = lid & 3;
    const int colbase = n0 + warp_n * 32 + 2 * lq;   // even
    float2 bia[4];
#pragma unroll
    for (int ni = 0; ni < 4; ni++) {
        bia[ni].x = __ldg(bias + colbase + ni * 8);
        bia[ni].y = __ldg(bias + colbase + ni * 8 + 1);
    }
#pragma unroll
    for (int mi = 0; mi < 2; mi++) {
#pragma unroll
        for (int h = 0; h < 2; h++) {
            const int row = m0 + warp_m * 32 + mi * 16 + h * 8 + l4;
            const int li = g_idx32[row];
            float* orow = out + (size_t)row * O_DIM;
            const __half2* lrow =
                (const __half2*)(g_lora + (size_t)row * O_DIM + colbase);
#pragma unroll
            for (int ni = 0; ni < 4; ni++) {
                const int col = colbase + ni * 8;
                float v0 = acc[mi][ni][h * 2 + 0] + bia[ni].x;
                float v1 = acc[mi][ni][h * 2 + 1] + bia[ni].y;
                if (li >= 0) {
                    __half2 hv = lrow[ni * 4];
                    v0 += __low2float(hv);
                    v1 += __high2float(hv);
                }
                *(float2*)(orow + col) = make_float2(v0, v1);
            }
        }
    }
}

// ---------------------------------------------------------------------------
// Stream/event resources: created LAZILY on first kernel_launch call (after
// the harness has initialized the CUDA context). No static-init CUDA calls.
// ---------------------------------------------------------------------------
namespace {
struct ForkJoin {
    cudaStream_t s1 = nullptr, s2 = nullptr;
    cudaEvent_t e0 = nullptr, e1 = nullptr, e2 = nullptr;
    bool ok = false;
    ForkJoin() {
        ok = (cudaStreamCreateWithFlags(&s1, cudaStreamNonBlocking) == cudaSuccess) &&
             (cudaStreamCreateWithFlags(&s2, cudaStreamNonBlocking) == cudaSuccess) &&
             (cudaEventCreateWithFlags(&e0, cudaEventDisableTiming) == cudaSuccess) &&
             (cudaEventCreateWithFlags(&e1, cudaEventDisableTiming) == cudaSuccess) &&
             (cudaEventCreateWithFlags(&e2, cudaEventDisableTiming) == cudaSuccess);
    }
};
}

// ---------------------------------------------------------------------------
extern "C" void kernel_launch(void* const* d_in, const int* in_sizes, int n_in,
                              void* d_out, int out_size) {
    const float* x      = (const float*)d_in[0];  // (T, H)
    const float* weight = (const float*)d_in[1];  // (O, H)
    const float* bias   = (const float*)d_in[2];  // (O,)
    const float* lora_a = (const float*)d_in[3];  // (L, R, H)
    const float* lora_b = (const float*)d_in[4];  // (L, O, R)
    const int*   rawidx = (const int*)d_in[5];    // (T,) int32 or int64
    float* out = (float*)d_out;                   // (T, O)

    // lazy one-time resources (constructed after CUDA context exists)
    static ForkJoin fj;

    cudaFuncSetAttribute(gemm_hmma, cudaFuncAttributeMaxDynamicSharedMemorySize,
                         DYN_SMEM);

    const int cx_blocks = (T_DIM * H_DIM / 4 + 255) / 256;
    const int cw_blocks = (O_DIM * H_DIM / 4 + 255) / 256;
    const dim3 sh_grid(L_DIM, SH_CH, SH_Z);
    const dim3 ex_grid(L_DIM, O_DIM / 512, EX_Z);
    const dim3 gm_grid(O_DIM / BN, T_DIM / BM);   // (64, 16) = 1024 tiles

    if (fj.ok) {
        // convert_w has no dependency on bucket -> fork immediately
        cudaEventRecord(fj.e0, 0);
        cudaStreamWaitEvent(fj.s1, fj.e0, 0);
        convert_w<<<cw_blocks, 256, 0, fj.s1>>>(weight);
        cudaEventRecord(fj.e1, fj.s1);

        // stream 0: bucket, then fork shrink->expand chain onto s2
        bucket_kernel<<<1, 256>>>(rawidx);
        cudaEventRecord(fj.e0, 0);
        cudaStreamWaitEvent(fj.s2, fj.e0, 0);
        shrink3<<<sh_grid, 256, 0, fj.s2>>>(x, lora_a);
        expand_kernel<<<ex_grid, 256, 0, fj.s2>>>(lora_b);
        cudaEventRecord(fj.e2, fj.s2);

        convert_x<<<cx_blocks, 256>>>(x);

        // join
        cudaStreamWaitEvent((cudaStream_t)0, fj.e1, 0);
        cudaStreamWaitEvent((cudaStream_t)0, fj.e2, 0);
    } else {
        convert_w<<<cw_blocks, 256>>>(weight);
        bucket_kernel<<<1, 256>>>(rawidx);
        shrink3<<<sh_grid, 256>>>(x, lora_a);
        expand_kernel<<<ex_grid, 256>>>(lora_b);
        convert_x<<<cx_blocks, 256>>>(x);
    }

    gemm_hmma<<<gm_grid, 256, DYN_SMEM>>>(bias, out);
}

// round 13
// speedup vs baseline: 6.3772x; 1.0395x over previous
#include <cuda_runtime.h>
#include <cuda_fp16.h>
#include <cstdint>

#define T_DIM 2048
#define H_DIM 4096
#define O_DIM 4096
#define L_DIM 32
#define R_DIM 16

#define BM 128
#define BN 64
#define BK 32
#define KT_N (H_DIM / BK)          // 128 k-tiles
#define STAGES 4
#define MAT_A_BYTES 8192           // 128 rows x 64 bytes
#define MAT_B_BYTES 4096           // 64 rows x 64 bytes
#define STAGE_BYTES (MAT_A_BYTES + MAT_B_BYTES)   // 12 KB
#define DYN_SMEM (STAGES * STAGE_BYTES)           // 48 KB

#define SH_CH 8                    // shrink H-chunks
#define SH_Z 8                     // shrink token-split
#define CHUNK4 (H_DIM / 4 / SH_CH) // 128 float4 per chunk
#define FX_Z 8                     // fixup token-split
#define FX_CHUNK 32                // staged tokens per round

// ---------------- device scratch ----------------
__device__ int    g_idx32[T_DIM];
__device__ int    g_tok[T_DIM];
__device__ int    g_cnt[L_DIM];
__device__ int    g_base[L_DIM];
__device__ float  g_shrunk[T_DIM * R_DIM];
__device__ __half g_Xhi[T_DIM * H_DIM];
__device__ __half g_Whi[O_DIM * H_DIM];

// ---------------- helpers ----------------
__device__ __forceinline__ uint32_t smem_u32(const void* p) {
    uint32_t a;
    asm("{ .reg .u64 t; cvta.to.shared.u64 t, %1; cvt.u32.u64 %0, t; }"
        : "=r"(a) : "l"(p));
    return a;
}

__device__ __forceinline__ uint32_t swz(uint32_t o) {
    return o ^ ((o >> 3) & 0x30);   // 64B-row swizzle
}

#define CP_ASYNC16(dst, src) \
    asm volatile("cp.async.cg.shared.global [%0], [%1], 16;" :: "r"(dst), "l"(src))
#define CP_COMMIT() asm volatile("cp.async.commit_group;" ::: "memory")
#define CP_WAIT2()  asm volatile("cp.async.wait_group 2;" ::: "memory")

#define LDSM4(d0, d1, d2, d3, a)                                          \
    asm volatile("ldmatrix.sync.aligned.m8n8.x4.shared.b16 {%0,%1,%2,%3}, [%4];" \
                 : "=r"(d0), "=r"(d1), "=r"(d2), "=r"(d3) : "r"(a))

__device__ __forceinline__ void mma16816h(float* c, const uint32_t* a,
                                          uint32_t b0, uint32_t b1) {
    asm volatile(
        "mma.sync.aligned.m16n8k16.row.col.f32.f16.f16.f32 "
        "{%0,%1,%2,%3}, {%4,%5,%6,%7}, {%8,%9}, {%0,%1,%2,%3};"
        : "+f"(c[0]), "+f"(c[1]), "+f"(c[2]), "+f"(c[3])
        : "r"(a[0]), "r"(a[1]), "r"(a[2]), "r"(a[3]), "r"(b0), "r"(b1));
}

// ---------------------------------------------------------------------------
// Kernel 1: index decode (int64 vs int32) + bucket tokens + zero g_shrunk.
// ---------------------------------------------------------------------------
__global__ void bucket_kernel(const int* __restrict__ raw) {
    __shared__ int bad;
    __shared__ int s_cnt[L_DIM];
    __shared__ int s_base[L_DIM];
    const int tid = threadIdx.x;
    if (tid == 0) bad = 0;
    if (tid < L_DIM) s_cnt[tid] = 0;
    __syncthreads();
    {   // 256 pairs = 2048 bytes, in-bounds for either width
        int lo = raw[2 * tid], hi = raw[2 * tid + 1];
        bool ok = (hi == 0 && lo >= 0) || (hi == -1 && lo < 0);
        if (!ok) bad = 1;
    }
    __syncthreads();
    const bool is64 = (bad == 0);
    for (int t = tid; t < T_DIM; t += 256) {
        int v = is64 ? raw[2 * t] : raw[t];
        g_idx32[t] = v;
        if (v >= 0) atomicAdd(&s_cnt[v], 1);
    }
    for (int i = tid; i < T_DIM * R_DIM / 4; i += 256)
        ((float4*)g_shrunk)[i] = make_float4(0, 0, 0, 0);
    __syncthreads();
    if (tid == 0) {
        int a = 0;
        for (int l = 0; l < L_DIM; l++) { s_base[l] = a; a += s_cnt[l]; }
    }
    __syncthreads();
    if (tid < L_DIM) {
        g_cnt[tid] = s_cnt[tid];
        g_base[tid] = s_base[tid];
        s_cnt[tid] = 0;
    }
    __syncthreads();
    for (int t = tid; t < T_DIM; t += 256) {
        int v = g_idx32[t];
        if (v >= 0) {
            int p = atomicAdd(&s_cnt[v], 1);
            g_tok[s_base[v] + p] = t;
        }
    }
}

// ---------------------------------------------------------------------------
// Kernel 2a: fp32 -> fp16 of X
// ---------------------------------------------------------------------------
__global__ void convert_x(const float* __restrict__ src) {
    int i = blockIdx.x * blockDim.x + threadIdx.x;
    if (i >= T_DIM * H_DIM / 4) return;
    float4 v = ((const float4*)src)[i];
    uint2 ph;
    ph.x = ((uint32_t)__half_as_ushort(__float2half(v.y)) << 16) |
           __half_as_ushort(__float2half(v.x));
    ph.y = ((uint32_t)__half_as_ushort(__float2half(v.w)) << 16) |
           __half_as_ushort(__float2half(v.z));
    ((uint2*)g_Xhi)[i] = ph;
}

// ---------------------------------------------------------------------------
// Kernel 2b: fp32 -> fp16 of W
// ---------------------------------------------------------------------------
__global__ void convert_w(const float* __restrict__ src) {
    int i = blockIdx.x * blockDim.x + threadIdx.x;
    if (i >= O_DIM * H_DIM / 4) return;
    float4 v = ((const float4*)src)[i];
    uint2 ph;
    ph.x = ((uint32_t)__half_as_ushort(__float2half(v.y)) << 16) |
           __half_as_ushort(__float2half(v.x));
    ph.y = ((uint32_t)__half_as_ushort(__float2half(v.w)) << 16) |
           __half_as_ushort(__float2half(v.z));
    ((uint2*)g_Whi)[i] = ph;
}

// ---------------------------------------------------------------------------
// Kernel 3: LoRA shrink, grid (32 adapters, 8 H-chunks, 8 token-slices).
//   Runs CONCURRENTLY with the GEMM (only fixup consumes g_shrunk).
// ---------------------------------------------------------------------------
__global__ __launch_bounds__(256) void shrink3(
    const float* __restrict__ x, const float* __restrict__ lora_a) {
    __shared__ float4 sA4[R_DIM * CHUNK4];       // 16 x 128 float4 = 32 KB
    const int l = blockIdx.x;
    const int n = g_cnt[l];
    if (n == 0) return;
    const int tid = threadIdx.x;
    const int wid = tid >> 5, lid = tid & 31;
    const int slot = blockIdx.z * 8 + wid;       // 0..SH_Z*8-1
    if (blockIdx.z * 8 >= n) return;             // whole block idle -> skip
    const int hb4 = blockIdx.y * CHUNK4;

    const float4* a4 = ((const float4*)lora_a) + (size_t)l * R_DIM * (H_DIM / 4);
    for (int i = tid; i < R_DIM * CHUNK4; i += 256) {
        int r = i / CHUNK4, j4 = i % CHUNK4;
        sA4[i] = a4[r * (H_DIM / 4) + hb4 + j4];
    }
    __syncthreads();

    const int base = g_base[l];
    for (int ti = slot; ti < n; ti += SH_Z * 8) {
        const int t = g_tok[base + ti];
        const float4* x4 = ((const float4*)x) + (size_t)t * (H_DIM / 4) + hb4;
        float4 xv[4];
#pragma unroll
        for (int j = 0; j < 4; j++) xv[j] = x4[lid + 32 * j];
        float acc[R_DIM];
#pragma unroll
        for (int r = 0; r < R_DIM; r++) acc[r] = 0.0f;
#pragma unroll
        for (int j = 0; j < 4; j++) {
#pragma unroll
            for (int r = 0; r < R_DIM; r++) {
                float4 av = sA4[r * CHUNK4 + lid + 32 * j];
                acc[r] += xv[j].x * av.x + xv[j].y * av.y +
                          xv[j].z * av.z + xv[j].w * av.w;
            }
        }
#pragma unroll
        for (int r = 0; r < R_DIM; r++) {
            float v = acc[r];
#pragma unroll
            for (int off = 16; off > 0; off >>= 1)
                v += __shfl_down_sync(0xffffffff, v, off);
            if (lid == 0) atomicAdd(&g_shrunk[t * R_DIM + r], v);
        }
    }
}

// ---------------------------------------------------------------------------
// Kernel 4: fp16 HMMA GEMM, single product, epilogue = acc + bias only.
//   128x64 tiles (1024 tiles -> 98.8% SM packing), 4-stage cp.async, occ 3.
// ---------------------------------------------------------------------------
__global__ void __launch_bounds__(256, 3) gemm_hmma(
    const float* __restrict__ bias, float* __restrict__ out) {
    extern __shared__ char dynsmem[];
    const uint32_t sbase = smem_u32(dynsmem);
    const int tid = threadIdx.x;
    const int wid = tid >> 5, lid = tid & 31;
    const int m0 = blockIdx.y * BM, n0 = blockIdx.x * BN;
    const int warp_m = wid & 3;        // 0..3 -> 32-row bands
    const int warp_n = wid >> 2;       // 0..1 -> 32-col bands

    const __half* gsrc[3];
    uint32_t sdst[3];
    {
        const __half* baseA = g_Xhi + (size_t)m0 * H_DIM;
        const __half* baseB = g_Whi + (size_t)n0 * H_DIM;
#pragma unroll
        for (int i = 0; i < 3; i++) {
            int c = tid + 256 * i;
            int mat = (c >= 512);
            int w = mat ? (c - 512) : c;
            int row = w >> 2, cq = w & 3;
            gsrc[i] = (mat ? baseB : baseA) + (size_t)row * H_DIM + cq * 8;
            sdst[i] = (mat ? MAT_A_BYTES : 0) + swz((uint32_t)(row * 64 + cq * 16));
        }
    }

#pragma unroll
    for (int s = 0; s < STAGES - 1; s++) {
        uint32_t sb = sbase + s * STAGE_BYTES;
#pragma unroll
        for (int i = 0; i < 3; i++) CP_ASYNC16(sb + sdst[i], gsrc[i] + s * BK);
        CP_COMMIT();
    }

    float acc[2][4][4];
#pragma unroll
    for (int a = 0; a < 2; a++)
#pragma unroll
        for (int b = 0; b < 4; b++)
#pragma unroll
            for (int c = 0; c < 4; c++) acc[a][b][c] = 0.0f;

    const uint32_t a_row = warp_m * 32 + (lid & 15);
    const uint32_t a_kb  = ((lid >> 4) & 1) * 16;
    const uint32_t b_row = warp_n * 32 + ((lid >> 4) & 1) * 8 + (lid & 7);
    const uint32_t b_kb  = ((lid >> 3) & 1) * 16;

#pragma unroll 1
    for (int kt = 0; kt < KT_N; kt++) {
        CP_WAIT2();
        __syncthreads();
        const int nt = kt + STAGES - 1;
        if (nt < KT_N) {
            uint32_t sb = sbase + (nt & 3) * STAGE_BYTES;
#pragma unroll
            for (int i = 0; i < 3; i++) CP_ASYNC16(sb + sdst[i], gsrc[i] + nt * BK);
        }
        CP_COMMIT();

        const uint32_t st = sbase + (kt & 3) * STAGE_BYTES;
#pragma unroll
        for (int kk = 0; kk < 2; kk++) {
            const uint32_t koff = kk * 32;
            uint32_t bh[2][4];
#pragma unroll
            for (int nj2 = 0; nj2 < 2; nj2++) {
                uint32_t o = swz((b_row + nj2 * 16) * 64 + koff + b_kb);
                LDSM4(bh[nj2][0], bh[nj2][1], bh[nj2][2], bh[nj2][3],
                      st + MAT_A_BYTES + o);
            }
#pragma unroll
            for (int mi = 0; mi < 2; mi++) {
                uint32_t ah[4];
                uint32_t o = swz((a_row + mi * 16) * 64 + koff + a_kb);
                LDSM4(ah[0], ah[1], ah[2], ah[3], st + o);
#pragma unroll
                for (int nj = 0; nj < 4; nj++) {
                    const uint32_t b0 = bh[nj >> 1][2 * (nj & 1)];
                    const uint32_t b1 = bh[nj >> 1][2 * (nj & 1) + 1];
                    mma16816h(acc[mi][nj], ah, b0, b1);
                }
            }
        }
    }

    // ---------------- epilogue: + bias only ----------------
    const int l4 = lid >> 2, lq = lid & 3;
    const int colbase = n0 + warp_n * 32 + 2 * lq;
    float2 bia[4];
#pragma unroll
    for (int ni = 0; ni < 4; ni++) {
        bia[ni].x = __ldg(bias + colbase + ni * 8);
        bia[ni].y = __ldg(bias + colbase + ni * 8 + 1);
    }
#pragma unroll
    for (int mi = 0; mi < 2; mi++) {
#pragma unroll
        for (int h = 0; h < 2; h++) {
            const int row = m0 + warp_m * 32 + mi * 16 + h * 8 + l4;
            float* orow = out + (size_t)row * O_DIM;
#pragma unroll
            for (int ni = 0; ni < 4; ni++) {
                const int col = colbase + ni * 8;
                *(float2*)(orow + col) =
                    make_float2(acc[mi][ni][h * 2 + 0] + bia[ni].x,
                                acc[mi][ni][h * 2 + 1] + bia[ni].y);
            }
        }
    }
}

// ---------------------------------------------------------------------------
// Kernel 5: LoRA fixup (post-GEMM): out[t, c] += shrunk[t,:] . B[l, c, :]
//   grid (32 adapters, 8 col-chunks of 512, 8 token-slices).
//   B cols in regs; shrunk staged in SMEM; RMW float2 on out.
// ---------------------------------------------------------------------------
__global__ __launch_bounds__(256) void fixup_kernel(
    const float* __restrict__ lora_b, float* __restrict__ out) {
    __shared__ float4 sS[FX_CHUNK][4];
    __shared__ int    sT[FX_CHUNK];
    const int l = blockIdx.x;
    const int n = g_cnt[l];
    const int z = blockIdx.z;
    if (z >= n) return;
    const int c0 = blockIdx.y * 512 + threadIdx.x * 2;

    const float4* b0 = (const float4*)(lora_b + ((size_t)l * O_DIM + c0) * R_DIM);
    const float4* b1 = (const float4*)(lora_b + ((size_t)l * O_DIM + c0 + 1) * R_DIM);
    float4 B0[4], B1[4];
#pragma unroll
    for (int q = 0; q < 4; q++) { B0[q] = b0[q]; B1[q] = b1[q]; }

    const int base = g_base[l];
    for (int ck = z; ck < n; ck += FX_Z * FX_CHUNK) {
        int cnt = (n - ck + FX_Z - 1) / FX_Z;
        if (cnt > FX_CHUNK) cnt = FX_CHUNK;
        __syncthreads();                       // prior round's reads done
        if (threadIdx.x < cnt * 4) {
            const int j = threadIdx.x >> 2, q = threadIdx.x & 3;
            const int t = g_tok[base + ck + j * FX_Z];
            if (q == 0) sT[j] = t;
            sS[j][q] = ((const float4*)g_shrunk)[t * 4 + q];
        }
        __syncthreads();
#pragma unroll 2
        for (int j = 0; j < cnt; j++) {
            const int t = sT[j];
            const float4 s0 = sS[j][0], s1 = sS[j][1];
            const float4 s2 = sS[j][2], s3 = sS[j][3];
            float d0a = s0.x * B0[0].x + s0.y * B0[0].y + s0.z * B0[0].z + s0.w * B0[0].w;
            float d0b = s1.x * B0[1].x + s1.y * B0[1].y + s1.z * B0[1].z + s1.w * B0[1].w;
            float d1a = s0.x * B1[0].x + s0.y * B1[0].y + s0.z * B1[0].z + s0.w * B1[0].w;
            float d1b = s1.x * B1[1].x + s1.y * B1[1].y + s1.z * B1[1].z + s1.w * B1[1].w;
            d0a += s2.x * B0[2].x + s2.y * B0[2].y + s2.z * B0[2].z + s2.w * B0[2].w;
            d0b += s3.x * B0[3].x + s3.y * B0[3].y + s3.z * B0[3].z + s3.w * B0[3].w;
            d1a += s2.x * B1[2].x + s2.y * B1[2].y + s2.z * B1[2].z + s2.w * B1[2].w;
            d1b += s3.x * B1[3].x + s3.y * B1[3].y + s3.z * B1[3].z + s3.w * B1[3].w;
            float2* op = (float2*)(out + (size_t)t * O_DIM + c0);
            float2 cur = *op;
            cur.x += d0a + d0b;
            cur.y += d1a + d1b;
            *op = cur;
        }
    }
}

// ---------------------------------------------------------------------------
// Stream/event resources: created LAZILY on first kernel_launch call.
// ---------------------------------------------------------------------------
namespace {
struct ForkJoin {
    cudaStream_t s1 = nullptr, s2 = nullptr;
    cudaEvent_t e0 = nullptr, e1 = nullptr, e2 = nullptr;
    bool ok = false;
    ForkJoin() {
        ok = (cudaStreamCreateWithFlags(&s1, cudaStreamNonBlocking) == cudaSuccess) &&
             (cudaStreamCreateWithFlags(&s2, cudaStreamNonBlocking) == cudaSuccess) &&
             (cudaEventCreateWithFlags(&e0, cudaEventDisableTiming) == cudaSuccess) &&
             (cudaEventCreateWithFlags(&e1, cudaEventDisableTiming) == cudaSuccess) &&
             (cudaEventCreateWithFlags(&e2, cudaEventDisableTiming) == cudaSuccess);
    }
};
}

// ---------------------------------------------------------------------------
extern "C" void kernel_launch(void* const* d_in, const int* in_sizes, int n_in,
                              void* d_out, int out_size) {
    const float* x      = (const float*)d_in[0];  // (T, H)
    const float* weight = (const float*)d_in[1];  // (O, H)
    const float* bias   = (const float*)d_in[2];  // (O,)
    const float* lora_a = (const float*)d_in[3];  // (L, R, H)
    const float* lora_b = (const float*)d_in[4];  // (L, O, R)
    const int*   rawidx = (const int*)d_in[5];    // (T,) int32 or int64
    float* out = (float*)d_out;                   // (T, O)

    // lazy one-time resources (constructed after CUDA context exists)
    static ForkJoin fj;

    cudaFuncSetAttribute(gemm_hmma, cudaFuncAttributeMaxDynamicSharedMemorySize,
                         DYN_SMEM);

    const int cx_blocks = (T_DIM * H_DIM / 4 + 255) / 256;
    const int cw_blocks = (O_DIM * H_DIM / 4 + 255) / 256;
    const dim3 sh_grid(L_DIM, SH_CH, SH_Z);
    const dim3 fx_grid(L_DIM, O_DIM / 512, FX_Z);
    const dim3 gm_grid(O_DIM / BN, T_DIM / BM);   // (64, 16) = 1024 tiles

    if (fj.ok) {
        // Fork at t=0: convert_w on s1, bucket->shrink on s2, convert_x on 0.
        cudaEventRecord(fj.e0, 0);
        cudaStreamWaitEvent(fj.s1, fj.e0, 0);
        cudaStreamWaitEvent(fj.s2, fj.e0, 0);

        convert_w<<<cw_blocks, 256, 0, fj.s1>>>(weight);
        cudaEventRecord(fj.e1, fj.s1);

        bucket_kernel<<<1, 256, 0, fj.s2>>>(rawidx);
        shrink3<<<sh_grid, 256, 0, fj.s2>>>(x, lora_a);   // overlaps the GEMM
        cudaEventRecord(fj.e2, fj.s2);

        convert_x<<<cx_blocks, 256>>>(x);

        // GEMM waits only on converts
        cudaStreamWaitEvent((cudaStream_t)0, fj.e1, 0);
        gemm_hmma<<<gm_grid, 256, DYN_SMEM>>>(bias, out);

        // fixup waits on GEMM (program order) + shrink (event)
        cudaStreamWaitEvent((cudaStream_t)0, fj.e2, 0);
        fixup_kernel<<<fx_grid, 256>>>(lora_b, out);
    } else {
        convert_w<<<cw_blocks, 256>>>(weight);
        bucket_kernel<<<1, 256>>>(rawidx);
        shrink3<<<sh_grid, 256>>>(x, lora_a);
        convert_x<<<cx_blocks, 256>>>(x);
        gemm_hmma<<<gm_grid, 256, DYN_SMEM>>>(bias, out);
        fixup_kernel<<<fx_grid, 256>>>(lora_b, out);
    }
}